// round 1
// baseline (speedup 1.0000x reference)
#include <cuda_runtime.h>

// ---------------------------------------------------------------------------
// TR_Linear: y = x @ W^T + bias, W built from tensor-ring cores.
// Factored form (avoids materializing W, halves GEMM FLOPs):
//   y[b, 4q+s] = sum_{k=(r2,r0)} M1[q,k] * T[b, s*256+k] + bias[4q+s]
//   T = x @ Bmat                                  (8192x1024)(1024x1024)
//   M1[q, r2*16+r0]          = sum_r1 core0[r0,q0,r1] * core1[r1,q1,r2]
//   Bmat[c, s*256+r2*16+r0]  = sum_r3 core2[r2, 16s+c/64, r3] * core3[r3, c%64, r0]
// ---------------------------------------------------------------------------

#define BM  128
#define BN  128
#define BKT 16
#define TM  8
#define TN  8

// Scratch (device globals: no allocation allowed in kernel_launch)
__device__ float g_M1T[256 * 1024];    // [k][q]   (transposed M1, row-major 256x1024)
__device__ float g_Bm [1024 * 1024];   // [c][n]   n = s*256 + r2*16 + r0
__device__ float g_T  [8192 * 1024];   // [b][n]

// ---------------------------------------------------------------------------
// Build M1^T: g_M1T[k*1024 + q] = sum_r1 core0[r0,q0,r1] * core1[r1,q1,r2]
//   k = r2*16 + r0, q = q0*32 + q1
// core0: (16,32,16) -> idx (r0*32+q0)*16+r1 ; core1: (16,32,16) -> (r1*32+q1)*16+r2
// ---------------------------------------------------------------------------
__global__ void build_m1(const float* __restrict__ c0, const float* __restrict__ c1) {
    int idx = blockIdx.x * blockDim.x + threadIdx.x;
    if (idx >= 1024 * 256) return;
    int q  = idx >> 8;
    int k  = idx & 255;
    int r2 = k >> 4, r0 = k & 15;
    int q0 = q >> 5, q1 = q & 31;
    float sum = 0.f;
#pragma unroll
    for (int r1 = 0; r1 < 16; ++r1)
        sum += __ldg(&c0[(r0 * 32 + q0) * 16 + r1]) * __ldg(&c1[(r1 * 32 + q1) * 16 + r2]);
    g_M1T[k * 1024 + q] = sum;
}

// ---------------------------------------------------------------------------
// Build Bmat: g_Bm[c*1024 + n] with n = s*256 + r2*16 + r0
//   o0 = s*16 + c/64, o1 = c%64
//   = sum_r3 core2[r2,o0,r3] * core3[r3,o1,r0]
// core2: (16,64,16) -> (r2*64+o0)*16+r3 ; core3: (16,64,16) -> (r3*64+o1)*16+r0
// ---------------------------------------------------------------------------
__global__ void build_bmat(const float* __restrict__ c2, const float* __restrict__ c3) {
    int idx = blockIdx.x * blockDim.x + threadIdx.x;
    if (idx >= 1024 * 1024) return;
    int c  = idx >> 10;
    int n  = idx & 1023;
    int s  = n >> 8;
    int k  = n & 255;
    int r2 = k >> 4, r0 = k & 15;
    int o0 = s * 16 + (c >> 6);
    int o1 = c & 63;
    float sum = 0.f;
#pragma unroll
    for (int r3 = 0; r3 < 16; ++r3)
        sum += __ldg(&c2[(r2 * 64 + o0) * 16 + r3]) * __ldg(&c3[(r3 * 64 + o1) * 16 + r0]);
    g_Bm[idx] = sum;
}

// ---------------------------------------------------------------------------
// Tiled SGEMM, C = A * B (both row-major), 128x128 tile, 8x8 per thread.
// MODE 0: A = x (8192x1024), B = g_Bm (1024x1024), C = g_T (8192x1024), K=1024
// MODE 1: A = g_T + z*256 (8192x256 slice, lda=1024), B = g_M1T (256x1024),
//         C = out with column map q -> 4q+z, + bias. K=256.
// ---------------------------------------------------------------------------
template <int MODE>
__global__ __launch_bounds__(256, 2)
void sgemm(const float* __restrict__ X, float* __restrict__ Out,
           const float* __restrict__ bias)
{
    constexpr int K = (MODE == 0) ? 1024 : 256;
    const float* A;
    const float* Bmat;
    if (MODE == 0) { A = X;                      Bmat = g_Bm;  }
    else           { A = g_T + blockIdx.z * 256; Bmat = g_M1T; }
    const int lda = 1024;
    const int ldb = 1024;

    __shared__ __align__(16) float As[BKT][BM];
    __shared__ __align__(16) float Bs[BKT][BN];

    const int tid = threadIdx.x;
    const int tr  = tid >> 4;      // 0..15
    const int tc  = tid & 15;      // 0..15
    const int rowBase = blockIdx.y * BM;
    const int colBase = blockIdx.x * BN;

    // cooperative load indices
    const int aRow = tid >> 2;           // 0..63
    const int aCol = (tid & 3) * 4;      // 0,4,8,12
    const int bRow = tid >> 5;           // 0..7
    const int bCol = (tid & 31) * 4;     // 0..124

    float acc[TM][TN] = {};

    for (int k0 = 0; k0 < K; k0 += BKT) {
        // A tile (BM x BKT), stored transposed As[k][m]
#pragma unroll
        for (int p = 0; p < 2; ++p) {
            float4 v = *(const float4*)(A + (size_t)(rowBase + aRow + p * 64) * lda + k0 + aCol);
            As[aCol + 0][aRow + p * 64] = v.x;
            As[aCol + 1][aRow + p * 64] = v.y;
            As[aCol + 2][aRow + p * 64] = v.z;
            As[aCol + 3][aRow + p * 64] = v.w;
        }
        // B tile (BKT x BN), direct
#pragma unroll
        for (int p = 0; p < 2; ++p) {
            *(float4*)&Bs[bRow + p * 8][bCol] =
                *(const float4*)(Bmat + (size_t)(k0 + bRow + p * 8) * ldb + colBase + bCol);
        }
        __syncthreads();

#pragma unroll
        for (int kk = 0; kk < BKT; ++kk) {
            float a[TM], b[TN];
#pragma unroll
            for (int i = 0; i < TM; ++i) a[i] = As[kk][tr * TM + i];
#pragma unroll
            for (int j = 0; j < TN; ++j) b[j] = Bs[kk][tc * TN + j];
#pragma unroll
            for (int i = 0; i < TM; ++i)
#pragma unroll
                for (int j = 0; j < TN; ++j)
                    acc[i][j] += a[i] * b[j];
        }
        __syncthreads();
    }

    if (MODE == 0) {
#pragma unroll
        for (int i = 0; i < TM; ++i) {
            int gr = rowBase + tr * TM + i;
#pragma unroll
            for (int j = 0; j < TN; j += 4) {
                float4 v = make_float4(acc[i][j], acc[i][j + 1], acc[i][j + 2], acc[i][j + 3]);
                *(float4*)(g_T + (size_t)gr * 1024 + colBase + tc * TN + j) = v;
            }
        }
    } else {
        const int s = blockIdx.z;
#pragma unroll
        for (int i = 0; i < TM; ++i) {
            int gr = rowBase + tr * TM + i;
#pragma unroll
            for (int j = 0; j < TN; ++j) {
                int q  = colBase + tc * TN + j;
                int oc = 4 * q + s;
                Out[(size_t)gr * 4096 + oc] = acc[i][j] + __ldg(&bias[oc]);
            }
        }
    }
}

// ---------------------------------------------------------------------------
extern "C" void kernel_launch(void* const* d_in, const int* in_sizes, int n_in,
                              void* d_out, int out_size)
{
    const float* x    = (const float*)d_in[0];  // (8192, 1024)
    const float* c0   = (const float*)d_in[1];  // (16,32,16)
    const float* c1   = (const float*)d_in[2];  // (16,32,16)
    const float* c2   = (const float*)d_in[3];  // (16,64,16)
    const float* c3   = (const float*)d_in[4];  // (16,64,16)
    const float* bias = (const float*)d_in[5];  // (4096,)
    float* out = (float*)d_out;                 // (8192, 4096) fp32

    build_m1  <<<1024, 256>>>(c0, c1);
    build_bmat<<<4096, 256>>>(c2, c3);

    // T = x @ Bmat
    sgemm<0><<<dim3(8, 64, 1), 256>>>(x, nullptr, nullptr);
    // y[:, 4q+s] = T_s @ M1^T + bias
    sgemm<1><<<dim3(8, 64, 4), 256>>>(nullptr, out, bias);
}

// round 3
// speedup vs baseline: 1.9389x; 1.9389x over previous
#include <cuda_runtime.h>
#include <cuda_bf16.h>
#include <cstdint>

// ===========================================================================
// TR_Linear via mma.sync (HMMA) bf16 split-precision GEMMs (no 'a'-gated PTX).
//   y[b, 4q+s] = sum_k M1[q,k] * T[b, s*256+k] + bias[4q+s]
//   T = x @ Bmat            (8192x1024)(1024x1024)
//   M1[q,k=(r2,r0)]     = sum_r1 core0[r0,q0,r1]*core1[r1,q1,r2]
//   BmT[n=(s,r2,r0), c] = sum_r3 core2[r2,16s+c/64,r3]*core3[r3,c%64,r0]
// GEMMs computed as D[m,n] = sum_k A[m,k]*B[n,k] with A,B split hi/lo bf16,
// D = Ah*Bh + Ah*Bl + Al*Bh  (error ~2^-18), fp32 accumulation.
// ===========================================================================

__device__ __nv_bfloat16 g_xhi[8192 * 1024];
__device__ __nv_bfloat16 g_xlo[8192 * 1024];
__device__ __nv_bfloat16 g_Thi[8192 * 1024];
__device__ __nv_bfloat16 g_Tlo[8192 * 1024];
__device__ __nv_bfloat16 g_Bhi[1024 * 1024];   // BmT[n][c]
__device__ __nv_bfloat16 g_Blo[1024 * 1024];
__device__ __nv_bfloat16 g_M1hi[1024 * 256];   // M1[q][k]
__device__ __nv_bfloat16 g_M1lo[1024 * 256];

// -------------------- helpers ----------------------------------------------
__device__ __forceinline__ uint32_t smem_u32(const void* p) {
    uint32_t a;
    asm("{ .reg .u64 t; cvta.to.shared.u64 t, %1; cvt.u32.u64 %0, t; }" : "=r"(a) : "l"(p));
    return a;
}
__device__ __forceinline__ uint32_t sw64(uint32_t off) { return off ^ ((off >> 3) & 0x30); }

__device__ __forceinline__ void cp16(uint32_t dst, const void* src) {
    asm volatile("cp.async.cg.shared.global [%0], [%1], 16;" :: "r"(dst), "l"(src));
}
__device__ __forceinline__ void cp_commit() { asm volatile("cp.async.commit_group;" ::: "memory"); }
template <int N> __device__ __forceinline__ void cp_wait() {
    asm volatile("cp.async.wait_group %0;" :: "n"(N) : "memory");
}

__device__ __forceinline__ void ldmx4(uint32_t* r, uint32_t addr) {
    asm volatile("ldmatrix.sync.aligned.m8n8.x4.shared.b16 {%0,%1,%2,%3}, [%4];"
                 : "=r"(r[0]), "=r"(r[1]), "=r"(r[2]), "=r"(r[3]) : "r"(addr));
}
__device__ __forceinline__ void mma16816(float* d, const uint32_t* a, uint32_t b0, uint32_t b1) {
    asm volatile(
        "mma.sync.aligned.m16n8k16.row.col.f32.bf16.bf16.f32 "
        "{%0,%1,%2,%3}, {%4,%5,%6,%7}, {%8,%9}, {%0,%1,%2,%3};"
        : "+f"(d[0]), "+f"(d[1]), "+f"(d[2]), "+f"(d[3])
        : "r"(a[0]), "r"(a[1]), "r"(a[2]), "r"(a[3]), "r"(b0), "r"(b1));
}

__device__ __forceinline__ void split1(float v, __nv_bfloat16& h, __nv_bfloat16& l) {
    h = __float2bfloat16_rn(v);
    l = __float2bfloat16_rn(v - __bfloat162float(h));
}
__device__ __forceinline__ uint32_t pack2(__nv_bfloat16 a, __nv_bfloat16 b) {
    return (uint32_t)__bfloat16_as_ushort(a) | ((uint32_t)__bfloat16_as_ushort(b) << 16);
}

// -------------------- prep kernels -----------------------------------------
__global__ void split_x_k(const float* __restrict__ x) {
    int i = blockIdx.x * blockDim.x + threadIdx.x;   // per float4, 2097152 total
    float4 v = ((const float4*)x)[i];
    __nv_bfloat16 h0, l0, h1, l1, h2, l2, h3, l3;
    split1(v.x, h0, l0); split1(v.y, h1, l1); split1(v.z, h2, l2); split1(v.w, h3, l3);
    ((uint2*)g_xhi)[i] = make_uint2(pack2(h0, h1), pack2(h2, h3));
    ((uint2*)g_xlo)[i] = make_uint2(pack2(l0, l1), pack2(l2, l3));
}

__global__ void build_m1_k(const float* __restrict__ c0, const float* __restrict__ c1) {
    int idx = blockIdx.x * blockDim.x + threadIdx.x;   // q*256+k
    int q = idx >> 8, k = idx & 255;
    int r2 = k >> 4, r0 = k & 15;
    int q0 = q >> 5, q1 = q & 31;
    float sum = 0.f;
#pragma unroll
    for (int r1 = 0; r1 < 16; ++r1)
        sum += __ldg(&c0[(r0 * 32 + q0) * 16 + r1]) * __ldg(&c1[(r1 * 32 + q1) * 16 + r2]);
    __nv_bfloat16 h, l; split1(sum, h, l);
    g_M1hi[idx] = h; g_M1lo[idx] = l;
}

__global__ void build_bmt_k(const float* __restrict__ c2, const float* __restrict__ c3) {
    int idx = blockIdx.x * blockDim.x + threadIdx.x;   // n*1024+c
    int n = idx >> 10, c = idx & 1023;
    int s = n >> 8, k = n & 255;
    int r2 = k >> 4, r0 = k & 15;
    int o0 = s * 16 + (c >> 6);
    int o1 = c & 63;
    float sum = 0.f;
#pragma unroll
    for (int r3 = 0; r3 < 16; ++r3)
        sum += __ldg(&c2[(r2 * 64 + o0) * 16 + r3]) * __ldg(&c3[(r3 * 64 + o1) * 16 + r0]);
    __nv_bfloat16 h, l; split1(sum, h, l);
    g_Bhi[idx] = h; g_Blo[idx] = l;
}

// ===========================================================================
// GEMM: CTA 128x128, BK=32, 8 warps (2x4), warp tile 64x32, double-buffered.
// SMEM stage (32KB): Ah(8K) Al(8K) Bh(8K) Bl(8K); tiles 128 rows x 64B, SW64.
// MODE 0: A=x(hi/lo) lda=1024, B=BmT(hi/lo) ldb=1024, K=1024 -> T hi/lo
// MODE 1: A=T(hi/lo)+z*256 lda=1024, B=M1(hi/lo) ldb=256, K=256 -> Out+bias
// ===========================================================================
#define GSMEM (1024 + 2 * 32768)

template <int MODE>
__global__ void __launch_bounds__(256, 1) gemm_k(float* __restrict__ Out,
                                                 const float* __restrict__ bias) {
    extern __shared__ char smem[];
    const uint32_t db = (smem_u32(smem) + 1023) & ~1023u;
    const int tid = threadIdx.x, lane = tid & 31, wid = tid >> 5;
    const int warp_m = wid & 1, warp_n = wid >> 1;
    const int rowBase = blockIdx.y * 128, colBase = blockIdx.x * 128;

    constexpr int LDA = 1024;
    constexpr int LDB = (MODE == 0) ? 1024 : 256;
    constexpr int NCH = (MODE == 0) ? 32 : 8;

    const __nv_bfloat16 *Ah, *Al, *Bh, *Bl;
    if (MODE == 0) {
        Ah = g_xhi + (size_t)rowBase * 1024;
        Al = g_xlo + (size_t)rowBase * 1024;
        Bh = g_Bhi + (size_t)colBase * 1024;
        Bl = g_Blo + (size_t)colBase * 1024;
    } else {
        Ah = g_Thi + (size_t)rowBase * 1024 + blockIdx.z * 256;
        Al = g_Tlo + (size_t)rowBase * 1024 + blockIdx.z * 256;
        Bh = g_M1hi + (size_t)colBase * 256;
        Bl = g_M1lo + (size_t)colBase * 256;
    }

    auto load_chunk = [&](int kc, int buf) {
        uint32_t base = db + buf * 32768;
#pragma unroll
        for (int it = 0; it < 2; ++it) {
            int idx = tid + it * 256;          // 0..511
            int row = idx >> 2, c16 = idx & 3; // row 0..127, 16B col 0..3
            uint32_t so = sw64((uint32_t)(row * 64 + c16 * 16));
            int aoff = row * LDA + kc * 32 + c16 * 8;
            int boff = row * LDB + kc * 32 + c16 * 8;
            cp16(base + so,         Ah + aoff);
            cp16(base + 8192 + so,  Al + aoff);
            cp16(base + 16384 + so, Bh + boff);
            cp16(base + 24576 + so, Bl + boff);
        }
        cp_commit();
    };

    float acc[4][4][4];
#pragma unroll
    for (int i = 0; i < 4; ++i)
#pragma unroll
        for (int j = 0; j < 4; ++j)
#pragma unroll
            for (int t = 0; t < 4; ++t) acc[i][j][t] = 0.f;

    // ldmatrix lane addressing (tile-local element offsets)
    const int rowA = warp_m * 64 + (lane & 15);            // + mt*16
    const int a_c16half = (lane >> 4) & 1;                 // + ks*2
    const int rowB = warp_n * 32 + (lane & 7) + ((lane >> 4) << 3);  // + nt16*16
    const int b_c16half = (lane >> 3) & 1;                 // + ks*2

    load_chunk(0, 0);

    for (int i = 0; i < NCH; ++i) {
        if (i + 1 < NCH) { load_chunk(i + 1, (i + 1) & 1); cp_wait<1>(); }
        else             { cp_wait<0>(); }
        __syncthreads();

        uint32_t base = db + (i & 1) * 32768;
#pragma unroll
        for (int ks = 0; ks < 2; ++ks) {
            uint32_t ah[4][4], al[4][4];
#pragma unroll
            for (int mt = 0; mt < 4; ++mt) {
                uint32_t off = sw64((uint32_t)((rowA + mt * 16) * 64 + (ks * 2 + a_c16half) * 16));
                ldmx4(ah[mt], base + off);
                ldmx4(al[mt], base + 8192 + off);
            }
            uint32_t bh[4][2], bl[4][2];
#pragma unroll
            for (int nt = 0; nt < 2; ++nt) {
                uint32_t off = sw64((uint32_t)((rowB + nt * 16) * 64 + (ks * 2 + b_c16half) * 16));
                uint32_t r[4];
                ldmx4(r, base + 16384 + off);
                bh[nt * 2][0] = r[0]; bh[nt * 2][1] = r[1];
                bh[nt * 2 + 1][0] = r[2]; bh[nt * 2 + 1][1] = r[3];
                ldmx4(r, base + 24576 + off);
                bl[nt * 2][0] = r[0]; bl[nt * 2][1] = r[1];
                bl[nt * 2 + 1][0] = r[2]; bl[nt * 2 + 1][1] = r[3];
            }
#pragma unroll
            for (int mt = 0; mt < 4; ++mt)
#pragma unroll
                for (int j = 0; j < 4; ++j) {
                    mma16816(acc[mt][j], ah[mt], bh[j][0], bh[j][1]);
                    mma16816(acc[mt][j], ah[mt], bl[j][0], bl[j][1]);
                    mma16816(acc[mt][j], al[mt], bh[j][0], bh[j][1]);
                }
        }
        __syncthreads();
    }

    // ------------------------- epilogue ------------------------------------
    const int r0base = rowBase + warp_m * 64 + (lane >> 2);
    const int cbase  = colBase + warp_n * 32 + (lane & 3) * 2;

    if (MODE == 0) {
#pragma unroll
        for (int mt = 0; mt < 4; ++mt)
#pragma unroll
            for (int j = 0; j < 4; ++j) {
                int r0 = r0base + mt * 16;
                int c  = cbase + j * 8;
                __nv_bfloat16 h0, l0, h1, l1;
                split1(acc[mt][j][0], h0, l0); split1(acc[mt][j][1], h1, l1);
                *(uint32_t*)(g_Thi + (size_t)r0 * 1024 + c) = pack2(h0, h1);
                *(uint32_t*)(g_Tlo + (size_t)r0 * 1024 + c) = pack2(l0, l1);
                split1(acc[mt][j][2], h0, l0); split1(acc[mt][j][3], h1, l1);
                *(uint32_t*)(g_Thi + (size_t)(r0 + 8) * 1024 + c) = pack2(h0, h1);
                *(uint32_t*)(g_Tlo + (size_t)(r0 + 8) * 1024 + c) = pack2(l0, l1);
            }
    } else {
        const int s = blockIdx.z;
#pragma unroll
        for (int mt = 0; mt < 4; ++mt)
#pragma unroll
            for (int j = 0; j < 4; ++j) {
                int r0 = r0base + mt * 16;
                int q  = cbase + j * 8;
                int oc0 = 4 * q + s, oc1 = 4 * (q + 1) + s;
                float b0 = __ldg(bias + oc0), b1 = __ldg(bias + oc1);
                float* p0 = Out + (size_t)r0 * 4096;
                float* p1 = Out + (size_t)(r0 + 8) * 4096;
                p0[oc0] = acc[mt][j][0] + b0;
                p0[oc1] = acc[mt][j][1] + b1;
                p1[oc0] = acc[mt][j][2] + b0;
                p1[oc1] = acc[mt][j][3] + b1;
            }
    }
}

// ---------------------------------------------------------------------------
extern "C" void kernel_launch(void* const* d_in, const int* in_sizes, int n_in,
                              void* d_out, int out_size)
{
    const float* x    = (const float*)d_in[0];  // (8192, 1024)
    const float* c0   = (const float*)d_in[1];  // (16,32,16)
    const float* c1   = (const float*)d_in[2];  // (16,32,16)
    const float* c2   = (const float*)d_in[3];  // (16,64,16)
    const float* c3   = (const float*)d_in[4];  // (16,64,16)
    const float* bias = (const float*)d_in[5];  // (4096,)
    float* out = (float*)d_out;                 // (8192, 4096) fp32

    cudaFuncSetAttribute(gemm_k<0>, cudaFuncAttributeMaxDynamicSharedMemorySize, GSMEM);
    cudaFuncSetAttribute(gemm_k<1>, cudaFuncAttributeMaxDynamicSharedMemorySize, GSMEM);

    split_x_k  <<<8192, 256>>>(x);
    build_m1_k <<<1024, 256>>>(c0, c1);
    build_bmt_k<<<4096, 256>>>(c2, c3);

    gemm_k<0><<<dim3(8, 64, 1), 256, GSMEM>>>(nullptr, nullptr);
    gemm_k<1><<<dim3(8, 64, 4), 256, GSMEM>>>(out, bias);
}

// round 4
// speedup vs baseline: 2.0711x; 1.0682x over previous
#include <cuda_runtime.h>
#include <cuda_bf16.h>
#include <cstdint>

// ===========================================================================
// TR_Linear via mma.sync (HMMA) bf16 split-precision GEMMs.
//   y[b, 4q+s] = sum_k M1[q,k] * T[b, s*256+k] + bias[4q+s]
//   T = x @ Bmat            (8192x1024)(1024x1024)
//   M1[q,k=(r2,r0)]     = sum_r1 core0[r0,q0,r1]*core1[r1,q1,r2]
//   BmT[n=(s,r2,r0), c] = sum_r3 core2[r2,16s+c/64,r3]*core3[r3,c%64,r0]
// GEMMs: D[m,n] = sum_k A[m,k]*B[n,k], A,B split hi/lo bf16,
// D = Ah*Bh + Ah*Bl + Al*Bh (error ~1e-5), fp32 accumulation.
// 4-stage cp.async pipeline; MODE1 grid places the 4 s-CTAs of a q-tile
// adjacently so stride-4 output writes merge in L2.
// ===========================================================================

__device__ __nv_bfloat16 g_xhi[8192 * 1024];
__device__ __nv_bfloat16 g_xlo[8192 * 1024];
__device__ __nv_bfloat16 g_Thi[8192 * 1024];
__device__ __nv_bfloat16 g_Tlo[8192 * 1024];
__device__ __nv_bfloat16 g_Bhi[1024 * 1024];   // BmT[n][c]
__device__ __nv_bfloat16 g_Blo[1024 * 1024];
__device__ __nv_bfloat16 g_M1hi[1024 * 256];   // M1[q][k]
__device__ __nv_bfloat16 g_M1lo[1024 * 256];

// -------------------- helpers ----------------------------------------------
__device__ __forceinline__ uint32_t smem_u32(const void* p) {
    uint32_t a;
    asm("{ .reg .u64 t; cvta.to.shared.u64 t, %1; cvt.u32.u64 %0, t; }" : "=r"(a) : "l"(p));
    return a;
}
__device__ __forceinline__ uint32_t sw64(uint32_t off) { return off ^ ((off >> 3) & 0x30); }

__device__ __forceinline__ void cp16(uint32_t dst, const void* src) {
    asm volatile("cp.async.cg.shared.global [%0], [%1], 16;" :: "r"(dst), "l"(src));
}
__device__ __forceinline__ void cp_commit() { asm volatile("cp.async.commit_group;" ::: "memory"); }
template <int N> __device__ __forceinline__ void cp_wait() {
    asm volatile("cp.async.wait_group %0;" :: "n"(N) : "memory");
}

__device__ __forceinline__ void ldmx4(uint32_t* r, uint32_t addr) {
    asm volatile("ldmatrix.sync.aligned.m8n8.x4.shared.b16 {%0,%1,%2,%3}, [%4];"
                 : "=r"(r[0]), "=r"(r[1]), "=r"(r[2]), "=r"(r[3]) : "r"(addr));
}
__device__ __forceinline__ void mma16816(float* d, const uint32_t* a, uint32_t b0, uint32_t b1) {
    asm volatile(
        "mma.sync.aligned.m16n8k16.row.col.f32.bf16.bf16.f32 "
        "{%0,%1,%2,%3}, {%4,%5,%6,%7}, {%8,%9}, {%0,%1,%2,%3};"
        : "+f"(d[0]), "+f"(d[1]), "+f"(d[2]), "+f"(d[3])
        : "r"(a[0]), "r"(a[1]), "r"(a[2]), "r"(a[3]), "r"(b0), "r"(b1));
}

__device__ __forceinline__ void split1(float v, __nv_bfloat16& h, __nv_bfloat16& l) {
    h = __float2bfloat16_rn(v);
    l = __float2bfloat16_rn(v - __bfloat162float(h));
}
__device__ __forceinline__ uint32_t pack2(__nv_bfloat16 a, __nv_bfloat16 b) {
    return (uint32_t)__bfloat16_as_ushort(a) | ((uint32_t)__bfloat16_as_ushort(b) << 16);
}

// -------------------- prep kernels -----------------------------------------
__global__ void split_x_k(const float* __restrict__ x) {
    int i = blockIdx.x * blockDim.x + threadIdx.x;   // per float4
    float4 v = ((const float4*)x)[i];
    __nv_bfloat16 h0, l0, h1, l1, h2, l2, h3, l3;
    split1(v.x, h0, l0); split1(v.y, h1, l1); split1(v.z, h2, l2); split1(v.w, h3, l3);
    ((uint2*)g_xhi)[i] = make_uint2(pack2(h0, h1), pack2(h2, h3));
    ((uint2*)g_xlo)[i] = make_uint2(pack2(l0, l1), pack2(l2, l3));
}

__global__ void build_m1_k(const float* __restrict__ c0, const float* __restrict__ c1) {
    int idx = blockIdx.x * blockDim.x + threadIdx.x;   // q*256+k
    int q = idx >> 8, k = idx & 255;
    int r2 = k >> 4, r0 = k & 15;
    int q0 = q >> 5, q1 = q & 31;
    float sum = 0.f;
#pragma unroll
    for (int r1 = 0; r1 < 16; ++r1)
        sum += __ldg(&c0[(r0 * 32 + q0) * 16 + r1]) * __ldg(&c1[(r1 * 32 + q1) * 16 + r2]);
    __nv_bfloat16 h, l; split1(sum, h, l);
    g_M1hi[idx] = h; g_M1lo[idx] = l;
}

__global__ void build_bmt_k(const float* __restrict__ c2, const float* __restrict__ c3) {
    int idx = blockIdx.x * blockDim.x + threadIdx.x;   // n*1024+c
    int n = idx >> 10, c = idx & 1023;
    int s = n >> 8, k = n & 255;
    int r2 = k >> 4, r0 = k & 15;
    int o0 = s * 16 + (c >> 6);
    int o1 = c & 63;
    float sum = 0.f;
#pragma unroll
    for (int r3 = 0; r3 < 16; ++r3)
        sum += __ldg(&c2[(r2 * 64 + o0) * 16 + r3]) * __ldg(&c3[(r3 * 64 + o1) * 16 + r0]);
    __nv_bfloat16 h, l; split1(sum, h, l);
    g_Bhi[idx] = h; g_Blo[idx] = l;
}

// ===========================================================================
// GEMM: CTA 128x128, BK=32, 8 warps (2x4), warp tile 64x32, 4-stage pipeline.
// SMEM stage (32KB): Ah(8K) Al(8K) Bh(8K) Bl(8K); tiles 128 rows x 64B, SW64.
// MODE 0: A=x(hi/lo) lda=1024, B=BmT(hi/lo) ldb=1024, K=1024 -> T hi/lo
// MODE 1: A=T(hi/lo)+s*256 lda=1024, B=M1(hi/lo) ldb=256, K=256 -> Out+bias
//         grid.x = 32: s = bx&3, qblk = bx>>2 (s-CTAs adjacent -> L2 merge)
// ===========================================================================
#define STAGE_BYTES 32768
#define NSTAGES 4
#define GSMEM (1024 + NSTAGES * STAGE_BYTES)

template <int MODE>
__global__ void __launch_bounds__(256, 1) gemm_k(float* __restrict__ Out,
                                                 const float* __restrict__ bias) {
    extern __shared__ char smem[];
    const uint32_t db = (smem_u32(smem) + 1023) & ~1023u;
    const int tid = threadIdx.x, lane = tid & 31, wid = tid >> 5;
    const int warp_m = wid & 1, warp_n = wid >> 1;

    int rowBase, colBase, s;
    if (MODE == 0) { rowBase = blockIdx.y * 128; colBase = blockIdx.x * 128; s = 0; }
    else           { rowBase = blockIdx.y * 128; colBase = (blockIdx.x >> 2) * 128; s = blockIdx.x & 3; }

    constexpr int LDA = 1024;
    constexpr int LDB = (MODE == 0) ? 1024 : 256;
    constexpr int NCH = (MODE == 0) ? 32 : 8;

    const __nv_bfloat16 *Ah, *Al, *Bh, *Bl;
    if (MODE == 0) {
        Ah = g_xhi + (size_t)rowBase * 1024;
        Al = g_xlo + (size_t)rowBase * 1024;
        Bh = g_Bhi + (size_t)colBase * 1024;
        Bl = g_Blo + (size_t)colBase * 1024;
    } else {
        Ah = g_Thi + (size_t)rowBase * 1024 + s * 256;
        Al = g_Tlo + (size_t)rowBase * 1024 + s * 256;
        Bh = g_M1hi + (size_t)colBase * 256;
        Bl = g_M1lo + (size_t)colBase * 256;
    }

    auto load_chunk = [&](int kc, int buf) {
        uint32_t base = db + buf * STAGE_BYTES;
#pragma unroll
        for (int it = 0; it < 2; ++it) {
            int idx = tid + it * 256;          // 0..511
            int row = idx >> 2, c16 = idx & 3; // row 0..127, 16B col 0..3
            uint32_t so = sw64((uint32_t)(row * 64 + c16 * 16));
            int aoff = row * LDA + kc * 32 + c16 * 8;
            int boff = row * LDB + kc * 32 + c16 * 8;
            cp16(base + so,         Ah + aoff);
            cp16(base + 8192 + so,  Al + aoff);
            cp16(base + 16384 + so, Bh + boff);
            cp16(base + 24576 + so, Bl + boff);
        }
        cp_commit();
    };

    float acc[4][4][4];
#pragma unroll
    for (int i = 0; i < 4; ++i)
#pragma unroll
        for (int j = 0; j < 4; ++j)
#pragma unroll
            for (int t = 0; t < 4; ++t) acc[i][j][t] = 0.f;

    // ldmatrix lane addressing (tile-local)
    const int rowA = warp_m * 64 + (lane & 15);                       // + mt*16
    const int a_c16half = (lane >> 4) & 1;                            // + ks*2
    const int rowB = warp_n * 32 + (lane & 7) + ((lane >> 4) << 3);   // + nt*16
    const int b_c16half = (lane >> 3) & 1;                            // + ks*2

    // prologue: 3 stages in flight
    load_chunk(0, 0);
    load_chunk(1, 1);
    load_chunk(2, 2);

    for (int i = 0; i < NCH; ++i) {
        if (i < NCH - 2)      cp_wait<2>();
        else if (i == NCH - 2) cp_wait<1>();
        else                   cp_wait<0>();
        __syncthreads();
        if (i + 3 < NCH) load_chunk(i + 3, (i + 3) & (NSTAGES - 1));

        uint32_t base = db + (i & (NSTAGES - 1)) * STAGE_BYTES;
#pragma unroll
        for (int ks = 0; ks < 2; ++ks) {
            uint32_t ah[4][4], al[4][4];
#pragma unroll
            for (int mt = 0; mt < 4; ++mt) {
                uint32_t off = sw64((uint32_t)((rowA + mt * 16) * 64 + (ks * 2 + a_c16half) * 16));
                ldmx4(ah[mt], base + off);
                ldmx4(al[mt], base + 8192 + off);
            }
            uint32_t bh[4][2], bl[4][2];
#pragma unroll
            for (int nt = 0; nt < 2; ++nt) {
                uint32_t off = sw64((uint32_t)((rowB + nt * 16) * 64 + (ks * 2 + b_c16half) * 16));
                uint32_t r[4];
                ldmx4(r, base + 16384 + off);
                bh[nt * 2][0] = r[0]; bh[nt * 2][1] = r[1];
                bh[nt * 2 + 1][0] = r[2]; bh[nt * 2 + 1][1] = r[3];
                ldmx4(r, base + 24576 + off);
                bl[nt * 2][0] = r[0]; bl[nt * 2][1] = r[1];
                bl[nt * 2 + 1][0] = r[2]; bl[nt * 2 + 1][1] = r[3];
            }
#pragma unroll
            for (int mt = 0; mt < 4; ++mt)
#pragma unroll
                for (int j = 0; j < 4; ++j) {
                    mma16816(acc[mt][j], ah[mt], bh[j][0], bh[j][1]);
                    mma16816(acc[mt][j], ah[mt], bl[j][0], bl[j][1]);
                    mma16816(acc[mt][j], al[mt], bh[j][0], bh[j][1]);
                }
        }
        __syncthreads();
    }

    // ------------------------- epilogue ------------------------------------
    const int r0base = rowBase + warp_m * 64 + (lane >> 2);
    const int cbase  = colBase + warp_n * 32 + (lane & 3) * 2;

    if (MODE == 0) {
#pragma unroll
        for (int mt = 0; mt < 4; ++mt)
#pragma unroll
            for (int j = 0; j < 4; ++j) {
                int r0 = r0base + mt * 16;
                int c  = cbase + j * 8;
                __nv_bfloat16 h0, l0, h1, l1;
                split1(acc[mt][j][0], h0, l0); split1(acc[mt][j][1], h1, l1);
                *(uint32_t*)(g_Thi + (size_t)r0 * 1024 + c) = pack2(h0, h1);
                *(uint32_t*)(g_Tlo + (size_t)r0 * 1024 + c) = pack2(l0, l1);
                split1(acc[mt][j][2], h0, l0); split1(acc[mt][j][3], h1, l1);
                *(uint32_t*)(g_Thi + (size_t)(r0 + 8) * 1024 + c) = pack2(h0, h1);
                *(uint32_t*)(g_Tlo + (size_t)(r0 + 8) * 1024 + c) = pack2(l0, l1);
            }
    } else {
#pragma unroll
        for (int mt = 0; mt < 4; ++mt)
#pragma unroll
            for (int j = 0; j < 4; ++j) {
                int r0 = r0base + mt * 16;
                int q  = cbase + j * 8;
                int oc0 = 4 * q + s, oc1 = 4 * (q + 1) + s;
                float b0 = __ldg(bias + oc0), b1 = __ldg(bias + oc1);
                float* p0 = Out + (size_t)r0 * 4096;
                float* p1 = Out + (size_t)(r0 + 8) * 4096;
                p0[oc0] = acc[mt][j][0] + b0;
                p0[oc1] = acc[mt][j][1] + b1;
                p1[oc0] = acc[mt][j][2] + b0;
                p1[oc1] = acc[mt][j][3] + b1;
            }
    }
}

// ---------------------------------------------------------------------------
extern "C" void kernel_launch(void* const* d_in, const int* in_sizes, int n_in,
                              void* d_out, int out_size)
{
    const float* x    = (const float*)d_in[0];  // (8192, 1024)
    const float* c0   = (const float*)d_in[1];  // (16,32,16)
    const float* c1   = (const float*)d_in[2];  // (16,32,16)
    const float* c2   = (const float*)d_in[3];  // (16,64,16)
    const float* c3   = (const float*)d_in[4];  // (16,64,16)
    const float* bias = (const float*)d_in[5];  // (4096,)
    float* out = (float*)d_out;                 // (8192, 4096) fp32

    cudaFuncSetAttribute(gemm_k<0>, cudaFuncAttributeMaxDynamicSharedMemorySize, GSMEM);
    cudaFuncSetAttribute(gemm_k<1>, cudaFuncAttributeMaxDynamicSharedMemorySize, GSMEM);

    split_x_k  <<<8192, 256>>>(x);
    build_m1_k <<<1024, 256>>>(c0, c1);
    build_bmt_k<<<4096, 256>>>(c2, c3);

    gemm_k<0><<<dim3(8, 64, 1), 256, GSMEM>>>(nullptr, nullptr);
    // grid.x = 8 qblocks * 4 s; the 4 s-CTAs of one q-tile are adjacent
    gemm_k<1><<<dim3(32, 64, 1), 256, GSMEM>>>(out, bias);
}

// round 5
// speedup vs baseline: 3.6321x; 1.7537x over previous
#include <cuda_runtime.h>
#include <cuda_fp16.h>
#include <cstdint>

// ===========================================================================
// TR_Linear via single-precision fp16 HMMA GEMMs (fp32 accumulate).
//   y[b, 4q+s] = sum_k M1[q,k] * T[b, s*256+k] + bias[4q+s]
//   T = x @ Bmat            (8192x1024)(1024x1024)
//   M1[q,k=(r2,r0)]     = sum_r1 core0[r0,q0,r1]*core1[r1,q1,r2]
//   BmT[n=(s,r2,r0), c] = sum_r3 core2[r2,16s+c/64,r3]*core3[r3,c%64,r0]
// fp16 operands, fp32 accumulation: expected rel_err ~4e-4 (norm), < 1e-3.
// 4-stage cp.async pipeline, 2 CTAs/SM (128 regs), 16KB stages.
// MODE1 grid places the 4 s-CTAs of a q-tile adjacently (L2 write merge).
// ===========================================================================

__device__ __half g_xh[8192 * 1024];
__device__ __half g_Th[8192 * 1024];
__device__ __half g_Bh[1024 * 1024];   // BmT[n][c]
__device__ __half g_M1[1024 * 256];    // M1[q][k]

// -------------------- helpers ----------------------------------------------
__device__ __forceinline__ uint32_t smem_u32(const void* p) {
    uint32_t a;
    asm("{ .reg .u64 t; cvta.to.shared.u64 t, %1; cvt.u32.u64 %0, t; }" : "=r"(a) : "l"(p));
    return a;
}
__device__ __forceinline__ uint32_t sw64(uint32_t off) { return off ^ ((off >> 3) & 0x30); }

__device__ __forceinline__ void cp16(uint32_t dst, const void* src) {
    asm volatile("cp.async.cg.shared.global [%0], [%1], 16;" :: "r"(dst), "l"(src));
}
__device__ __forceinline__ void cp_commit() { asm volatile("cp.async.commit_group;" ::: "memory"); }
template <int N> __device__ __forceinline__ void cp_wait() {
    asm volatile("cp.async.wait_group %0;" :: "n"(N) : "memory");
}

__device__ __forceinline__ void ldmx4(uint32_t* r, uint32_t addr) {
    asm volatile("ldmatrix.sync.aligned.m8n8.x4.shared.b16 {%0,%1,%2,%3}, [%4];"
                 : "=r"(r[0]), "=r"(r[1]), "=r"(r[2]), "=r"(r[3]) : "r"(addr));
}
__device__ __forceinline__ void mma16816(float* d, const uint32_t* a, uint32_t b0, uint32_t b1) {
    asm volatile(
        "mma.sync.aligned.m16n8k16.row.col.f32.f16.f16.f32 "
        "{%0,%1,%2,%3}, {%4,%5,%6,%7}, {%8,%9}, {%0,%1,%2,%3};"
        : "+f"(d[0]), "+f"(d[1]), "+f"(d[2]), "+f"(d[3])
        : "r"(a[0]), "r"(a[1]), "r"(a[2]), "r"(a[3]), "r"(b0), "r"(b1));
}
__device__ __forceinline__ uint32_t pack2h(__half a, __half b) {
    return (uint32_t)__half_as_ushort(a) | ((uint32_t)__half_as_ushort(b) << 16);
}

// -------------------- prep kernels -----------------------------------------
__global__ void cvt_x_k(const float* __restrict__ x) {
    int i = blockIdx.x * blockDim.x + threadIdx.x;   // per float4
    float4 v = ((const float4*)x)[i];
    ((uint2*)g_xh)[i] = make_uint2(pack2h(__float2half_rn(v.x), __float2half_rn(v.y)),
                                   pack2h(__float2half_rn(v.z), __float2half_rn(v.w)));
}

__global__ void build_m1_k(const float* __restrict__ c0, const float* __restrict__ c1) {
    int idx = blockIdx.x * blockDim.x + threadIdx.x;   // q*256+k
    int q = idx >> 8, k = idx & 255;
    int r2 = k >> 4, r0 = k & 15;
    int q0 = q >> 5, q1 = q & 31;
    float sum = 0.f;
#pragma unroll
    for (int r1 = 0; r1 < 16; ++r1)
        sum += __ldg(&c0[(r0 * 32 + q0) * 16 + r1]) * __ldg(&c1[(r1 * 32 + q1) * 16 + r2]);
    g_M1[idx] = __float2half_rn(sum);
}

__global__ void build_bmt_k(const float* __restrict__ c2, const float* __restrict__ c3) {
    int idx = blockIdx.x * blockDim.x + threadIdx.x;   // n*1024+c
    int n = idx >> 10, c = idx & 1023;
    int s = n >> 8, k = n & 255;
    int r2 = k >> 4, r0 = k & 15;
    int o0 = s * 16 + (c >> 6);
    int o1 = c & 63;
    float sum = 0.f;
#pragma unroll
    for (int r3 = 0; r3 < 16; ++r3)
        sum += __ldg(&c2[(r2 * 64 + o0) * 16 + r3]) * __ldg(&c3[(r3 * 64 + o1) * 16 + r0]);
    g_Bh[idx] = __float2half_rn(sum);
}

// ===========================================================================
// GEMM: CTA 128x128, BK=32, 8 warps (2x4), warp tile 64x32, 4-stage pipeline.
// SMEM stage (16KB): A(8K) B(8K); tiles 128 rows x 64B (32 fp16), SW64.
// MODE 0: A=g_xh lda=1024, B=g_Bh ldb=1024, K=1024 -> g_Th
// MODE 1: A=g_Th+s*256 lda=1024, B=g_M1 ldb=256, K=256 -> Out+bias
//         grid.x = 32: s = bx&3, qblk = bx>>2
// ===========================================================================
#define STAGE_BYTES 16384
#define NSTAGES 4
#define GSMEM (1024 + NSTAGES * STAGE_BYTES)

template <int MODE>
__global__ void __launch_bounds__(256, 2) gemm_k(float* __restrict__ Out,
                                                 const float* __restrict__ bias) {
    extern __shared__ char smem[];
    const uint32_t db = (smem_u32(smem) + 1023) & ~1023u;
    const int tid = threadIdx.x, lane = tid & 31, wid = tid >> 5;
    const int warp_m = wid & 1, warp_n = wid >> 1;

    int rowBase, colBase, s;
    if (MODE == 0) { rowBase = blockIdx.y * 128; colBase = blockIdx.x * 128; s = 0; }
    else           { rowBase = blockIdx.y * 128; colBase = (blockIdx.x >> 2) * 128; s = blockIdx.x & 3; }

    constexpr int LDA = 1024;
    constexpr int LDB = (MODE == 0) ? 1024 : 256;
    constexpr int NCH = (MODE == 0) ? 32 : 8;

    const __half *A, *B;
    if (MODE == 0) {
        A = g_xh + (size_t)rowBase * 1024;
        B = g_Bh + (size_t)colBase * 1024;
    } else {
        A = g_Th + (size_t)rowBase * 1024 + s * 256;
        B = g_M1 + (size_t)colBase * 256;
    }

    auto load_chunk = [&](int kc, int buf) {
        uint32_t base = db + buf * STAGE_BYTES;
#pragma unroll
        for (int it = 0; it < 2; ++it) {
            int idx = tid + it * 256;          // 0..511
            int row = idx >> 2, c16 = idx & 3; // row 0..127, 16B col 0..3
            uint32_t so = sw64((uint32_t)(row * 64 + c16 * 16));
            cp16(base + so,        A + row * LDA + kc * 32 + c16 * 8);
            cp16(base + 8192 + so, B + row * LDB + kc * 32 + c16 * 8);
        }
        cp_commit();
    };

    float acc[4][4][4];
#pragma unroll
    for (int i = 0; i < 4; ++i)
#pragma unroll
        for (int j = 0; j < 4; ++j)
#pragma unroll
            for (int t = 0; t < 4; ++t) acc[i][j][t] = 0.f;

    // ldmatrix lane addressing (tile-local)
    const int rowA = warp_m * 64 + (lane & 15);                       // + mt*16
    const int a_c16half = (lane >> 4) & 1;                            // + ks*2
    const int rowB = warp_n * 32 + (lane & 7) + ((lane >> 4) << 3);   // + nt*16
    const int b_c16half = (lane >> 3) & 1;                            // + ks*2

    load_chunk(0, 0);
    load_chunk(1, 1);
    load_chunk(2, 2);

    for (int i = 0; i < NCH; ++i) {
        if (i < NCH - 2)       cp_wait<2>();
        else if (i == NCH - 2) cp_wait<1>();
        else                   cp_wait<0>();
        __syncthreads();
        if (i + 3 < NCH) load_chunk(i + 3, (i + 3) & (NSTAGES - 1));

        uint32_t base = db + (i & (NSTAGES - 1)) * STAGE_BYTES;
#pragma unroll
        for (int ks = 0; ks < 2; ++ks) {
            uint32_t a[4][4];
#pragma unroll
            for (int mt = 0; mt < 4; ++mt) {
                uint32_t off = sw64((uint32_t)((rowA + mt * 16) * 64 + (ks * 2 + a_c16half) * 16));
                ldmx4(a[mt], base + off);
            }
            uint32_t b[4][2];
#pragma unroll
            for (int nt = 0; nt < 2; ++nt) {
                uint32_t off = sw64((uint32_t)((rowB + nt * 16) * 64 + (ks * 2 + b_c16half) * 16));
                uint32_t r[4];
                ldmx4(r, base + 8192 + off);
                b[nt * 2][0] = r[0];     b[nt * 2][1] = r[1];
                b[nt * 2 + 1][0] = r[2]; b[nt * 2 + 1][1] = r[3];
            }
#pragma unroll
            for (int mt = 0; mt < 4; ++mt)
#pragma unroll
                for (int j = 0; j < 4; ++j)
                    mma16816(acc[mt][j], a[mt], b[j][0], b[j][1]);
        }
        __syncthreads();
    }

    // ------------------------- epilogue ------------------------------------
    const int r0base = rowBase + warp_m * 64 + (lane >> 2);
    const int cbase  = colBase + warp_n * 32 + (lane & 3) * 2;

    if (MODE == 0) {
#pragma unroll
        for (int mt = 0; mt < 4; ++mt)
#pragma unroll
            for (int j = 0; j < 4; ++j) {
                int r0 = r0base + mt * 16;
                int c  = cbase + j * 8;
                *(uint32_t*)(g_Th + (size_t)r0 * 1024 + c) =
                    pack2h(__float2half_rn(acc[mt][j][0]), __float2half_rn(acc[mt][j][1]));
                *(uint32_t*)(g_Th + (size_t)(r0 + 8) * 1024 + c) =
                    pack2h(__float2half_rn(acc[mt][j][2]), __float2half_rn(acc[mt][j][3]));
            }
    } else {
#pragma unroll
        for (int mt = 0; mt < 4; ++mt)
#pragma unroll
            for (int j = 0; j < 4; ++j) {
                int r0 = r0base + mt * 16;
                int q  = cbase + j * 8;
                int oc0 = 4 * q + s, oc1 = 4 * (q + 1) + s;
                float b0 = __ldg(bias + oc0), b1 = __ldg(bias + oc1);
                float* p0 = Out + (size_t)r0 * 4096;
                float* p1 = Out + (size_t)(r0 + 8) * 4096;
                p0[oc0] = acc[mt][j][0] + b0;
                p0[oc1] = acc[mt][j][1] + b1;
                p1[oc0] = acc[mt][j][2] + b0;
                p1[oc1] = acc[mt][j][3] + b1;
            }
    }
}

// ---------------------------------------------------------------------------
extern "C" void kernel_launch(void* const* d_in, const int* in_sizes, int n_in,
                              void* d_out, int out_size)
{
    const float* x    = (const float*)d_in[0];  // (8192, 1024)
    const float* c0   = (const float*)d_in[1];  // (16,32,16)
    const float* c1   = (const float*)d_in[2];  // (16,32,16)
    const float* c2   = (const float*)d_in[3];  // (16,64,16)
    const float* c3   = (const float*)d_in[4];  // (16,64,16)
    const float* bias = (const float*)d_in[5];  // (4096,)
    float* out = (float*)d_out;                 // (8192, 4096) fp32

    cudaFuncSetAttribute(gemm_k<0>, cudaFuncAttributeMaxDynamicSharedMemorySize, GSMEM);
    cudaFuncSetAttribute(gemm_k<1>, cudaFuncAttributeMaxDynamicSharedMemorySize, GSMEM);

    cvt_x_k    <<<8192, 256>>>(x);
    build_m1_k <<<1024, 256>>>(c0, c1);
    build_bmt_k<<<4096, 256>>>(c2, c3);

    gemm_k<0><<<dim3(8, 64, 1), 256, GSMEM>>>(nullptr, nullptr);
    gemm_k<1><<<dim3(32, 64, 1), 256, GSMEM>>>(out, bias);
}

// round 7
// speedup vs baseline: 5.0040x; 1.3777x over previous
#include <cuda_runtime.h>
#include <cuda_fp16.h>
#include <cstdint>

// ===========================================================================
// TR_Linear via fp16 HMMA GEMMs (fp32 accumulate).
//   y[b, 4q+s] = sum_k M1[q,k] * T[b, s*256+k] + bias[4q+s]
//   T = x @ Bmat            (8192x1024)(1024x1024)
// GEMM2: one CTA owns 128 rows x 128 contiguous out cols (32 q x 4 s);
// warps = (warp_m, warp_s); M1 q-tile smem-resident; epilogue interleaves
// (q,s)->4q+s via padded smem -> fully coalesced float4 stores.
// ===========================================================================

__device__ __half g_xh[8192 * 1024];
__device__ __half g_Th[8192 * 1024];
__device__ __half g_Bh[1024 * 1024];   // BmT[n][c]
__device__ __half g_M1[1024 * 256];    // M1[q][k]

// -------------------- helpers ----------------------------------------------
__device__ __forceinline__ uint32_t smem_u32(const void* p) {
    uint32_t a;
    asm("{ .reg .u64 t; cvta.to.shared.u64 t, %1; cvt.u32.u64 %0, t; }" : "=r"(a) : "l"(p));
    return a;
}
__device__ __forceinline__ uint32_t sw64(uint32_t off) { return off ^ ((off >> 3) & 0x30); }

__device__ __forceinline__ void cp16(uint32_t dst, const void* src) {
    asm volatile("cp.async.cg.shared.global [%0], [%1], 16;" :: "r"(dst), "l"(src));
}
__device__ __forceinline__ void cp_commit() { asm volatile("cp.async.commit_group;" ::: "memory"); }
template <int N> __device__ __forceinline__ void cp_wait() {
    asm volatile("cp.async.wait_group %0;" :: "n"(N) : "memory");
}

__device__ __forceinline__ void ldmx4(uint32_t* r, uint32_t addr) {
    asm volatile("ldmatrix.sync.aligned.m8n8.x4.shared.b16 {%0,%1,%2,%3}, [%4];"
                 : "=r"(r[0]), "=r"(r[1]), "=r"(r[2]), "=r"(r[3]) : "r"(addr));
}
__device__ __forceinline__ void mma16816(float* d, const uint32_t* a, uint32_t b0, uint32_t b1) {
    asm volatile(
        "mma.sync.aligned.m16n8k16.row.col.f32.f16.f16.f32 "
        "{%0,%1,%2,%3}, {%4,%5,%6,%7}, {%8,%9}, {%0,%1,%2,%3};"
        : "+f"(d[0]), "+f"(d[1]), "+f"(d[2]), "+f"(d[3])
        : "r"(a[0]), "r"(a[1]), "r"(a[2]), "r"(a[3]), "r"(b0), "r"(b1));
}
__device__ __forceinline__ uint32_t pack2h(__half a, __half b) {
    return (uint32_t)__half_as_ushort(a) | ((uint32_t)__half_as_ushort(b) << 16);
}

// -------------------- prep kernels -----------------------------------------
__global__ void cvt_x_k(const float* __restrict__ x) {
    int i = blockIdx.x * blockDim.x + threadIdx.x;
    float4 v = ((const float4*)x)[i];
    ((uint2*)g_xh)[i] = make_uint2(pack2h(__float2half_rn(v.x), __float2half_rn(v.y)),
                                   pack2h(__float2half_rn(v.z), __float2half_rn(v.w)));
}

__global__ void build_m1_k(const float* __restrict__ c0, const float* __restrict__ c1) {
    int idx = blockIdx.x * blockDim.x + threadIdx.x;   // q*256+k
    int q = idx >> 8, k = idx & 255;
    int r2 = k >> 4, r0 = k & 15;
    int q0 = q >> 5, q1 = q & 31;
    float sum = 0.f;
#pragma unroll
    for (int r1 = 0; r1 < 16; ++r1)
        sum += __ldg(&c0[(r0 * 32 + q0) * 16 + r1]) * __ldg(&c1[(r1 * 32 + q1) * 16 + r2]);
    g_M1[idx] = __float2half_rn(sum);
}

__global__ void build_bmt_k(const float* __restrict__ c2, const float* __restrict__ c3) {
    int idx = blockIdx.x * blockDim.x + threadIdx.x;   // n*1024+c
    int n = idx >> 10, c = idx & 1023;
    int s = n >> 8, k = n & 255;
    int r2 = k >> 4, r0 = k & 15;
    int o0 = s * 16 + (c >> 6);
    int o1 = c & 63;
    float sum = 0.f;
#pragma unroll
    for (int r3 = 0; r3 < 16; ++r3)
        sum += __ldg(&c2[(r2 * 64 + o0) * 16 + r3]) * __ldg(&c3[(r3 * 64 + o1) * 16 + r0]);
    g_Bh[idx] = __float2half_rn(sum);
}

// ===========================================================================
// GEMM1: T = x @ BmT^T. CTA 128x128, BK=32, 8 warps (2x4), 4-stage pipeline.
// (unchanged from round 5 — verified, 58us)
// ===========================================================================
#define STAGE_BYTES 16384
#define NSTAGES 4
#define G1SMEM (1024 + NSTAGES * STAGE_BYTES)

__global__ void __launch_bounds__(256, 2) gemm1_k() {
    extern __shared__ char smem[];
    const uint32_t db = (smem_u32(smem) + 1023) & ~1023u;
    const int tid = threadIdx.x, lane = tid & 31, wid = tid >> 5;
    const int warp_m = wid & 1, warp_n = wid >> 1;
    const int rowBase = blockIdx.y * 128, colBase = blockIdx.x * 128;

    const __half* A = g_xh + (size_t)rowBase * 1024;
    const __half* B = g_Bh + (size_t)colBase * 1024;

    auto load_chunk = [&](int kc, int buf) {
        uint32_t base = db + buf * STAGE_BYTES;
#pragma unroll
        for (int it = 0; it < 2; ++it) {
            int idx = tid + it * 256;
            int row = idx >> 2, c16 = idx & 3;
            uint32_t so = sw64((uint32_t)(row * 64 + c16 * 16));
            cp16(base + so,        A + row * 1024 + kc * 32 + c16 * 8);
            cp16(base + 8192 + so, B + row * 1024 + kc * 32 + c16 * 8);
        }
        cp_commit();
    };

    float acc[4][4][4];
#pragma unroll
    for (int i = 0; i < 4; ++i)
#pragma unroll
        for (int j = 0; j < 4; ++j)
#pragma unroll
            for (int t = 0; t < 4; ++t) acc[i][j][t] = 0.f;

    const int rowA = warp_m * 64 + (lane & 15);
    const int a_c16half = (lane >> 4) & 1;
    const int rowB = warp_n * 32 + (lane & 7) + ((lane >> 4) << 3);
    const int b_c16half = (lane >> 3) & 1;

    load_chunk(0, 0); load_chunk(1, 1); load_chunk(2, 2);

    for (int i = 0; i < 32; ++i) {
        if (i < 30)       cp_wait<2>();
        else if (i == 30) cp_wait<1>();
        else              cp_wait<0>();
        __syncthreads();
        if (i + 3 < 32) load_chunk(i + 3, (i + 3) & (NSTAGES - 1));

        uint32_t base = db + (i & (NSTAGES - 1)) * STAGE_BYTES;
#pragma unroll
        for (int ks = 0; ks < 2; ++ks) {
            uint32_t a[4][4];
#pragma unroll
            for (int mt = 0; mt < 4; ++mt) {
                uint32_t off = sw64((uint32_t)((rowA + mt * 16) * 64 + (ks * 2 + a_c16half) * 16));
                ldmx4(a[mt], base + off);
            }
            uint32_t b[4][2];
#pragma unroll
            for (int nt = 0; nt < 2; ++nt) {
                uint32_t off = sw64((uint32_t)((rowB + nt * 16) * 64 + (ks * 2 + b_c16half) * 16));
                uint32_t r[4];
                ldmx4(r, base + 8192 + off);
                b[nt * 2][0] = r[0];     b[nt * 2][1] = r[1];
                b[nt * 2 + 1][0] = r[2]; b[nt * 2 + 1][1] = r[3];
            }
#pragma unroll
            for (int mt = 0; mt < 4; ++mt)
#pragma unroll
                for (int j = 0; j < 4; ++j)
                    mma16816(acc[mt][j], a[mt], b[j][0], b[j][1]);
        }
        __syncthreads();
    }

    const int r0base = rowBase + warp_m * 64 + (lane >> 2);
    const int cbase  = colBase + warp_n * 32 + (lane & 3) * 2;
#pragma unroll
    for (int mt = 0; mt < 4; ++mt)
#pragma unroll
        for (int j = 0; j < 4; ++j) {
            int r0 = r0base + mt * 16;
            int c  = cbase + j * 8;
            *(uint32_t*)(g_Th + (size_t)r0 * 1024 + c) =
                pack2h(__float2half_rn(acc[mt][j][0]), __float2half_rn(acc[mt][j][1]));
            *(uint32_t*)(g_Th + (size_t)(r0 + 8) * 1024 + c) =
                pack2h(__float2half_rn(acc[mt][j][2]), __float2half_rn(acc[mt][j][3]));
        }
}

// ===========================================================================
// GEMM2: out[b, 4q+s] = sum_k T[b, s*256+k] * M1[q,k] + bias
// CTA: 128 rows x 32 q x 4 s (=128 contiguous out cols). 8 warps =
// (warp_m in {0,1}) x (warp_s in {0..3}); warp tile 64 rows x 32 q, K=256.
// smem: B resident 16KB (8 kc-subtiles, 32q x 64B SW64) at Bs;
//       A double-buffered 2 x 32KB (4 s-subtiles x 128r x 64B SW64) at As,
//       classic 1-ahead double buffer (round-3 verified structure);
//       epilogue reuses As: 128 x 132 fp32 padded interleave buffer.
// ===========================================================================
#define EPI_PITCH 132
#define G2SMEM (1024 + 16384 + 128 * EPI_PITCH * 4)

__global__ void __launch_bounds__(256, 2) gemm2_k(float* __restrict__ Out,
                                                  const float* __restrict__ bias) {
    extern __shared__ char smem[];
    const uint32_t db = (smem_u32(smem) + 1023) & ~1023u;
    const uint32_t Bs = db;            // 16KB resident B
    const uint32_t As = db + 16384;    // 2 x 32KB A stages / epilogue buffer
    const int tid = threadIdx.x, lane = tid & 31, wid = tid >> 5;
    const int warp_m = wid & 1, warp_s = wid >> 1;
    const int rowBase = blockIdx.y * 128, qBase = blockIdx.x * 32;

    const __half* A  = g_Th + (size_t)rowBase * 1024;  // rows x [s*256 + k]
    const __half* Bm = g_M1 + (size_t)qBase * 256;     // 32 q x 256 k

    // --- resident B load: ALL 8 kc-subtiles (32 rows x 64B each, 16KB) ---
#pragma unroll
    for (int it = 0; it < 4; ++it) {
        int idx = tid + it * 256;          // 0..1023
        int kc = idx >> 7;                 // 0..7
        int r  = (idx >> 2) & 31;
        int c  = idx & 3;
        cp16(Bs + kc * 2048 + sw64((uint32_t)(r * 64 + c * 16)),
             Bm + r * 256 + kc * 32 + c * 8);
    }

    // --- A stage loader: 4 s-subtiles x 128 rows x 32 k (32KB) ---
    auto loadA = [&](int kc, int buf) {
        uint32_t base = As + buf * 32768;
#pragma unroll
        for (int it = 0; it < 8; ++it) {
            int idx = tid + it * 256;      // 0..2047
            int s   = idx >> 9;
            int row = (idx >> 2) & 127, c16 = idx & 3;
            cp16(base + s * 8192 + sw64((uint32_t)(row * 64 + c16 * 16)),
                 A + row * 1024 + s * 256 + kc * 32 + c16 * 8);
        }
        cp_commit();
    };

    loadA(0, 0);   // group 0 = B + A chunk 0

    float acc[4][4][4];
#pragma unroll
    for (int i = 0; i < 4; ++i)
#pragma unroll
        for (int j = 0; j < 4; ++j)
#pragma unroll
            for (int t = 0; t < 4; ++t) acc[i][j][t] = 0.f;

    const int rowA = warp_m * 64 + (lane & 15);
    const int a_c16half = (lane >> 4) & 1;
    const int rowB = (lane & 7) + ((lane >> 4) << 3);
    const int b_c16half = (lane >> 3) & 1;

    for (int i = 0; i < 8; ++i) {
        if (i + 1 < 8) { loadA(i + 1, (i + 1) & 1); cp_wait<1>(); }
        else           { cp_wait<0>(); }
        __syncthreads();

        uint32_t abase = As + (i & 1) * 32768 + warp_s * 8192;
        uint32_t bbase = Bs + i * 2048;
#pragma unroll
        for (int ks = 0; ks < 2; ++ks) {
            uint32_t a[4][4];
#pragma unroll
            for (int mt = 0; mt < 4; ++mt) {
                uint32_t off = sw64((uint32_t)((rowA + mt * 16) * 64 + (ks * 2 + a_c16half) * 16));
                ldmx4(a[mt], abase + off);
            }
            uint32_t b[4][2];
#pragma unroll
            for (int nt = 0; nt < 2; ++nt) {
                uint32_t off = sw64((uint32_t)((rowB + nt * 16) * 64 + (ks * 2 + b_c16half) * 16));
                uint32_t r[4];
                ldmx4(r, bbase + off);
                b[nt * 2][0] = r[0];     b[nt * 2][1] = r[1];
                b[nt * 2 + 1][0] = r[2]; b[nt * 2 + 1][1] = r[3];
            }
#pragma unroll
            for (int mt = 0; mt < 4; ++mt)
#pragma unroll
                for (int j = 0; j < 4; ++j)
                    mma16816(acc[mt][j], a[mt], b[j][0], b[j][1]);
        }
        __syncthreads();
    }

    // --- epilogue: interleave (q,s) -> 4q+s via padded smem ---
    {
        const int rloc  = warp_m * 64 + (lane >> 2);
        const int qloc0 = (lane & 3) * 2;
#pragma unroll
        for (int mt = 0; mt < 4; ++mt)
#pragma unroll
            for (int j = 0; j < 4; ++j) {
                int r0 = rloc + mt * 16;
                int q0 = qloc0 + j * 8;
                uint32_t a0 = As + (uint32_t)((r0)     * EPI_PITCH + 4 * q0 + warp_s) * 4;
                uint32_t a1 = As + (uint32_t)((r0)     * EPI_PITCH + 4 * (q0 + 1) + warp_s) * 4;
                uint32_t a2 = As + (uint32_t)((r0 + 8) * EPI_PITCH + 4 * q0 + warp_s) * 4;
                uint32_t a3 = As + (uint32_t)((r0 + 8) * EPI_PITCH + 4 * (q0 + 1) + warp_s) * 4;
                asm volatile("st.shared.f32 [%0], %1;" :: "r"(a0), "f"(acc[mt][j][0]));
                asm volatile("st.shared.f32 [%0], %1;" :: "r"(a1), "f"(acc[mt][j][1]));
                asm volatile("st.shared.f32 [%0], %1;" :: "r"(a2), "f"(acc[mt][j][2]));
                asm volatile("st.shared.f32 [%0], %1;" :: "r"(a3), "f"(acc[mt][j][3]));
            }
    }
    __syncthreads();

    // coalesced float4 stores with bias
    const int cbase = qBase * 4;   // 128 contiguous out cols
#pragma unroll
    for (int it = 0; it < 16; ++it) {
        int idx = tid + it * 256;          // 0..4095 float4s
        int row = idx >> 5, col4 = idx & 31;
        float4 v;
        uint32_t sa = As + (uint32_t)(row * EPI_PITCH + col4 * 4) * 4;
        asm volatile("ld.shared.v4.f32 {%0,%1,%2,%3}, [%4];"
                     : "=f"(v.x), "=f"(v.y), "=f"(v.z), "=f"(v.w) : "r"(sa));
        float4 bb = __ldg((const float4*)(bias + cbase + col4 * 4));
        v.x += bb.x; v.y += bb.y; v.z += bb.z; v.w += bb.w;
        *(float4*)(Out + (size_t)(rowBase + row) * 4096 + cbase + col4 * 4) = v;
    }
}

// ---------------------------------------------------------------------------
extern "C" void kernel_launch(void* const* d_in, const int* in_sizes, int n_in,
                              void* d_out, int out_size)
{
    const float* x    = (const float*)d_in[0];
    const float* c0   = (const float*)d_in[1];
    const float* c1   = (const float*)d_in[2];
    const float* c2   = (const float*)d_in[3];
    const float* c3   = (const float*)d_in[4];
    const float* bias = (const float*)d_in[5];
    float* out = (float*)d_out;

    cudaFuncSetAttribute(gemm1_k, cudaFuncAttributeMaxDynamicSharedMemorySize, G1SMEM);
    cudaFuncSetAttribute(gemm2_k, cudaFuncAttributeMaxDynamicSharedMemorySize, G2SMEM);

    cvt_x_k    <<<8192, 256>>>(x);
    build_m1_k <<<1024, 256>>>(c0, c1);
    build_bmt_k<<<4096, 256>>>(c2, c3);

    gemm1_k<<<dim3(8, 64, 1), 256, G1SMEM>>>();
    gemm2_k<<<dim3(32, 64, 1), 256, G2SMEM>>>(out, bias);
}

// round 9
// speedup vs baseline: 5.4941x; 1.0979x over previous
#include <cuda_runtime.h>
#include <cuda_fp16.h>
#include <cstdint>

// ===========================================================================
// TR_Linear via fp16 HMMA GEMMs (fp32 accumulate).
//   y[b, 4q+s] = sum_k M1[q,k] * T[b, s*256+k] + bias[4q+s]
//   T = x @ Bmat            (8192x1024)(1024x1024)
// gemm1: CTA 128x128, BK=32, 4-stage single-sync pipeline.
// gemm2: CTA 128 rows x 64 q x 4 s (256 contiguous out cols), 512 thr,
//        16 warps (2m x 2q x 4s), B resident 32KB, 3-stage single-sync A,
//        two-phase pitch-268 smem interleave epilogue -> coalesced stores.
// ===========================================================================

__device__ __half g_xh[8192 * 1024];
__device__ __half g_Th[8192 * 1024];
__device__ __half g_Bh[1024 * 1024];   // BmT[n][c]
__device__ __half g_M1[1024 * 256];    // M1[q][k]

// -------------------- helpers ----------------------------------------------
__device__ __forceinline__ uint32_t smem_u32(const void* p) {
    uint32_t a;
    asm("{ .reg .u64 t; cvta.to.shared.u64 t, %1; cvt.u32.u64 %0, t; }" : "=r"(a) : "l"(p));
    return a;
}
__device__ __forceinline__ uint32_t sw64(uint32_t off) { return off ^ ((off >> 3) & 0x30); }

__device__ __forceinline__ void cp16(uint32_t dst, const void* src) {
    asm volatile("cp.async.cg.shared.global [%0], [%1], 16;" :: "r"(dst), "l"(src));
}
__device__ __forceinline__ void cp_commit() { asm volatile("cp.async.commit_group;" ::: "memory"); }
template <int N> __device__ __forceinline__ void cp_wait() {
    asm volatile("cp.async.wait_group %0;" :: "n"(N) : "memory");
}

__device__ __forceinline__ void ldmx4(uint32_t* r, uint32_t addr) {
    asm volatile("ldmatrix.sync.aligned.m8n8.x4.shared.b16 {%0,%1,%2,%3}, [%4];"
                 : "=r"(r[0]), "=r"(r[1]), "=r"(r[2]), "=r"(r[3]) : "r"(addr));
}
__device__ __forceinline__ void mma16816(float* d, const uint32_t* a, uint32_t b0, uint32_t b1) {
    asm volatile(
        "mma.sync.aligned.m16n8k16.row.col.f32.f16.f16.f32 "
        "{%0,%1,%2,%3}, {%4,%5,%6,%7}, {%8,%9}, {%0,%1,%2,%3};"
        : "+f"(d[0]), "+f"(d[1]), "+f"(d[2]), "+f"(d[3])
        : "r"(a[0]), "r"(a[1]), "r"(a[2]), "r"(a[3]), "r"(b0), "r"(b1));
}
__device__ __forceinline__ uint32_t pack2h(__half a, __half b) {
    return (uint32_t)__half_as_ushort(a) | ((uint32_t)__half_as_ushort(b) << 16);
}

// -------------------- fused prep kernel ------------------------------------
// blocks [0,8192): cvt x -> fp16 ; [8192,12288): build BmT ; [12288,13312): M1
__global__ void prep_k(const float* __restrict__ x,
                       const float* __restrict__ c0, const float* __restrict__ c1,
                       const float* __restrict__ c2, const float* __restrict__ c3) {
    int b = blockIdx.x, tid = threadIdx.x;
    if (b < 8192) {
        int i = b * 256 + tid;
        float4 v = ((const float4*)x)[i];
        ((uint2*)g_xh)[i] = make_uint2(pack2h(__float2half_rn(v.x), __float2half_rn(v.y)),
                                       pack2h(__float2half_rn(v.z), __float2half_rn(v.w)));
    } else if (b < 12288) {
        int idx = (b - 8192) * 256 + tid;     // n*1024+c
        int n = idx >> 10, c = idx & 1023;
        int s = n >> 8, k = n & 255;
        int r2 = k >> 4, r0 = k & 15;
        int o0 = s * 16 + (c >> 6);
        int o1 = c & 63;
        float sum = 0.f;
#pragma unroll
        for (int r3 = 0; r3 < 16; ++r3)
            sum += __ldg(&c2[(r2 * 64 + o0) * 16 + r3]) * __ldg(&c3[(r3 * 64 + o1) * 16 + r0]);
        g_Bh[idx] = __float2half_rn(sum);
    } else {
        int idx = (b - 12288) * 256 + tid;    // q*256+k
        int q = idx >> 8, k = idx & 255;
        int r2 = k >> 4, r0 = k & 15;
        int q0 = q >> 5, q1 = q & 31;
        float sum = 0.f;
#pragma unroll
        for (int r1 = 0; r1 < 16; ++r1)
            sum += __ldg(&c0[(r0 * 32 + q0) * 16 + r1]) * __ldg(&c1[(r1 * 32 + q1) * 16 + r2]);
        g_M1[idx] = __float2half_rn(sum);
    }
}

// ===========================================================================
// GEMM1: T = x @ BmT^T. CTA 128x128, BK=32, 8 warps (2x4), 4-stage
// single-sync pipeline (prefetch distance 2).
// ===========================================================================
#define STAGE_BYTES 16384
#define NSTAGES 4
#define G1SMEM (1024 + NSTAGES * STAGE_BYTES)

__global__ void __launch_bounds__(256, 2) gemm1_k() {
    extern __shared__ char smem[];
    const uint32_t db = (smem_u32(smem) + 1023) & ~1023u;
    const int tid = threadIdx.x, lane = tid & 31, wid = tid >> 5;
    const int warp_m = wid & 1, warp_n = wid >> 1;
    const int rowBase = blockIdx.y * 128, colBase = blockIdx.x * 128;

    const __half* A = g_xh + (size_t)rowBase * 1024;
    const __half* B = g_Bh + (size_t)colBase * 1024;

    auto load_chunk = [&](int kc, int buf) {
        uint32_t base = db + buf * STAGE_BYTES;
#pragma unroll
        for (int it = 0; it < 2; ++it) {
            int idx = tid + it * 256;
            int row = idx >> 2, c16 = idx & 3;
            uint32_t so = sw64((uint32_t)(row * 64 + c16 * 16));
            cp16(base + so,        A + row * 1024 + kc * 32 + c16 * 8);
            cp16(base + 8192 + so, B + row * 1024 + kc * 32 + c16 * 8);
        }
        cp_commit();
    };

    float acc[4][4][4];
#pragma unroll
    for (int i = 0; i < 4; ++i)
#pragma unroll
        for (int j = 0; j < 4; ++j)
#pragma unroll
            for (int t = 0; t < 4; ++t) acc[i][j][t] = 0.f;

    const int rowA = warp_m * 64 + (lane & 15);
    const int a_c16half = (lane >> 4) & 1;
    const int rowB = warp_n * 32 + (lane & 7) + ((lane >> 4) << 3);
    const int b_c16half = (lane >> 3) & 1;

    load_chunk(0, 0);
    load_chunk(1, 1);

    for (int i = 0; i < 32; ++i) {
        if (i + 2 < 32) load_chunk(i + 2, (i + 2) & (NSTAGES - 1));
        if (i < 30)       cp_wait<2>();
        else if (i == 30) cp_wait<1>();
        else              cp_wait<0>();
        __syncthreads();

        uint32_t base = db + (i & (NSTAGES - 1)) * STAGE_BYTES;
#pragma unroll
        for (int ks = 0; ks < 2; ++ks) {
            uint32_t a[4][4];
#pragma unroll
            for (int mt = 0; mt < 4; ++mt) {
                uint32_t off = sw64((uint32_t)((rowA + mt * 16) * 64 + (ks * 2 + a_c16half) * 16));
                ldmx4(a[mt], base + off);
            }
            uint32_t b[4][2];
#pragma unroll
            for (int nt = 0; nt < 2; ++nt) {
                uint32_t off = sw64((uint32_t)((rowB + nt * 16) * 64 + (ks * 2 + b_c16half) * 16));
                uint32_t r[4];
                ldmx4(r, base + 8192 + off);
                b[nt * 2][0] = r[0];     b[nt * 2][1] = r[1];
                b[nt * 2 + 1][0] = r[2]; b[nt * 2 + 1][1] = r[3];
            }
#pragma unroll
            for (int mt = 0; mt < 4; ++mt)
#pragma unroll
                for (int j = 0; j < 4; ++j)
                    mma16816(acc[mt][j], a[mt], b[j][0], b[j][1]);
        }
    }

    const int r0base = rowBase + warp_m * 64 + (lane >> 2);
    const int cbase  = colBase + warp_n * 32 + (lane & 3) * 2;
#pragma unroll
    for (int mt = 0; mt < 4; ++mt)
#pragma unroll
        for (int j = 0; j < 4; ++j) {
            int r0 = r0base + mt * 16;
            int c  = cbase + j * 8;
            *(uint32_t*)(g_Th + (size_t)r0 * 1024 + c) =
                pack2h(__float2half_rn(acc[mt][j][0]), __float2half_rn(acc[mt][j][1]));
            *(uint32_t*)(g_Th + (size_t)(r0 + 8) * 1024 + c) =
                pack2h(__float2half_rn(acc[mt][j][2]), __float2half_rn(acc[mt][j][3]));
        }
}

// ===========================================================================
// GEMM2: out[b, 4q+s] = sum_k T[b, s*256+k] * M1[q,k] + bias
// CTA: 128 rows x 64 q x 4 s (256 contiguous out cols), 512 threads.
// 16 warps: warp_m = wid&1, warp_q = (wid>>1)&1, warp_s = wid>>2.
// Warp tile: 64 rows x 32 q, K=256 (warp's own s slice).
// smem: B resident 32KB (8 kc-subtiles of 64q x 64B SW64) at Bs;
//       A 3-stage x 32KB (4 s x 128r x 64B SW64), single-sync, dist-1;
//       epilogue reuses A region: two phases of 64 rows x pitch-268 fp32
//       (268 % 4 == 0 -> float4-aligned rows; 268 % 32 = 12 -> bank rotate).
// ===========================================================================
#define EPI_PITCH 268
#define G2SMEM (1024 + 32768 + 3 * 32768)

__global__ void __launch_bounds__(512, 1) gemm2_k(float* __restrict__ Out,
                                                  const float* __restrict__ bias) {
    extern __shared__ char smem[];
    const uint32_t db = (smem_u32(smem) + 1023) & ~1023u;
    const uint32_t Bs = db;             // 32KB resident B
    const uint32_t As = db + 32768;     // 3 x 32KB A stages / epilogue buffer
    const int tid = threadIdx.x, lane = tid & 31, wid = tid >> 5;
    const int warp_m = wid & 1, warp_q = (wid >> 1) & 1, warp_s = wid >> 2;
    const int rowBase = blockIdx.y * 128, qBase = blockIdx.x * 64;

    const __half* A  = g_Th + (size_t)rowBase * 1024;  // rows x [s*256 + k]
    const __half* Bm = g_M1 + (size_t)qBase * 256;     // 64 q x 256 k

    // --- resident B: 8 kc-subtiles of 64 rows x 64B (32KB, 2048 cp16) ---
#pragma unroll
    for (int it = 0; it < 4; ++it) {
        int idx = tid + it * 512;          // 0..2047
        int kc = idx >> 8;                 // 0..7 (256 cp16 each)
        int r  = (idx >> 2) & 63;
        int c  = idx & 3;
        cp16(Bs + kc * 4096 + sw64((uint32_t)(r * 64 + c * 16)),
             Bm + r * 256 + kc * 32 + c * 8);
    }

    // --- A stage: 4 s-subtiles x 128 rows x 32 k (32KB, 2048 cp16) ---
    auto loadA = [&](int kc, int buf) {
        uint32_t base = As + buf * 32768;
#pragma unroll
        for (int it = 0; it < 4; ++it) {
            int idx = tid + it * 512;      // 0..2047
            int s   = idx >> 9;
            int row = (idx >> 2) & 127, c16 = idx & 3;
            cp16(base + s * 8192 + sw64((uint32_t)(row * 64 + c16 * 16)),
                 A + row * 1024 + s * 256 + kc * 32 + c16 * 8);
        }
        cp_commit();
    };

    loadA(0, 0);   // group 0 = B + A chunk 0

    float acc[4][4][4];
#pragma unroll
    for (int i = 0; i < 4; ++i)
#pragma unroll
        for (int j = 0; j < 4; ++j)
#pragma unroll
            for (int t = 0; t < 4; ++t) acc[i][j][t] = 0.f;

    const int rowA = warp_m * 64 + (lane & 15);
    const int a_c16half = (lane >> 4) & 1;
    const int rowB = warp_q * 32 + (lane & 7) + ((lane >> 4) << 3);
    const int b_c16half = (lane >> 3) & 1;

    int bufi = 0;
    for (int i = 0; i < 8; ++i) {
        if (i + 1 < 8) {
            int nb = bufi + 1; if (nb == 3) nb = 0;
            loadA(i + 1, nb);
        }
        if (i < 7) cp_wait<1>(); else cp_wait<0>();
        __syncthreads();

        uint32_t abase = As + bufi * 32768 + warp_s * 8192;
        uint32_t bbase = Bs + i * 4096;
#pragma unroll
        for (int ks = 0; ks < 2; ++ks) {
            uint32_t a[4][4];
#pragma unroll
            for (int mt = 0; mt < 4; ++mt) {
                uint32_t off = sw64((uint32_t)((rowA + mt * 16) * 64 + (ks * 2 + a_c16half) * 16));
                ldmx4(a[mt], abase + off);
            }
            uint32_t b[4][2];
#pragma unroll
            for (int nt = 0; nt < 2; ++nt) {
                uint32_t off = sw64((uint32_t)((rowB + nt * 16) * 64 + (ks * 2 + b_c16half) * 16));
                uint32_t r[4];
                ldmx4(r, bbase + off);
                b[nt * 2][0] = r[0];     b[nt * 2][1] = r[1];
                b[nt * 2 + 1][0] = r[2]; b[nt * 2 + 1][1] = r[3];
            }
#pragma unroll
            for (int mt = 0; mt < 4; ++mt)
#pragma unroll
                for (int j = 0; j < 4; ++j)
                    mma16816(acc[mt][j], a[mt], b[j][0], b[j][1]);
        }
        if (++bufi == 3) bufi = 0;
    }

    // --- epilogue: two phases (64 rows each), pitch-268 interleave buffer ---
    const int cbase = qBase * 4;           // 256 contiguous out cols
#pragma unroll
    for (int p = 0; p < 2; ++p) {
        __syncthreads();                   // A-buffer reads (or prev phase) done
        if (warp_m == p) {
            const int brow0 = (lane >> 2);             // + mt*16 (+8)
            const int qloc0 = warp_q * 32 + (lane & 3) * 2;
#pragma unroll
            for (int mt = 0; mt < 4; ++mt)
#pragma unroll
                for (int j = 0; j < 4; ++j) {
                    int br = brow0 + mt * 16;
                    int q0 = qloc0 + j * 8;
                    uint32_t a0 = As + (uint32_t)(br       * EPI_PITCH + 4 * q0 + warp_s) * 4;
                    uint32_t a1 = As + (uint32_t)(br       * EPI_PITCH + 4 * (q0 + 1) + warp_s) * 4;
                    uint32_t a2 = As + (uint32_t)((br + 8) * EPI_PITCH + 4 * q0 + warp_s) * 4;
                    uint32_t a3 = As + (uint32_t)((br + 8) * EPI_PITCH + 4 * (q0 + 1) + warp_s) * 4;
                    asm volatile("st.shared.f32 [%0], %1;" :: "r"(a0), "f"(acc[mt][j][0]));
                    asm volatile("st.shared.f32 [%0], %1;" :: "r"(a1), "f"(acc[mt][j][1]));
                    asm volatile("st.shared.f32 [%0], %1;" :: "r"(a2), "f"(acc[mt][j][2]));
                    asm volatile("st.shared.f32 [%0], %1;" :: "r"(a3), "f"(acc[mt][j][3]));
                }
        }
        __syncthreads();
        // coalesced float4 stores with bias: 64 rows x 64 float4s
#pragma unroll
        for (int it = 0; it < 8; ++it) {
            int idx = tid + it * 512;      // 0..4095
            int row = idx >> 6, col4 = idx & 63;
            float4 v;
            uint32_t sa = As + (uint32_t)(row * EPI_PITCH + col4 * 4) * 4;
            asm volatile("ld.shared.v4.f32 {%0,%1,%2,%3}, [%4];"
                         : "=f"(v.x), "=f"(v.y), "=f"(v.z), "=f"(v.w) : "r"(sa));
            float4 bb = __ldg((const float4*)(bias + cbase + col4 * 4));
            v.x += bb.x; v.y += bb.y; v.z += bb.z; v.w += bb.w;
            *(float4*)(Out + (size_t)(rowBase + p * 64 + row) * 4096 + cbase + col4 * 4) = v;
        }
    }
}

// ---------------------------------------------------------------------------
extern "C" void kernel_launch(void* const* d_in, const int* in_sizes, int n_in,
                              void* d_out, int out_size)
{
    const float* x    = (const float*)d_in[0];
    const float* c0   = (const float*)d_in[1];
    const float* c1   = (const float*)d_in[2];
    const float* c2   = (const float*)d_in[3];
    const float* c3   = (const float*)d_in[4];
    const float* bias = (const float*)d_in[5];
    float* out = (float*)d_out;

    cudaFuncSetAttribute(gemm1_k, cudaFuncAttributeMaxDynamicSharedMemorySize, G1SMEM);
    cudaFuncSetAttribute(gemm2_k, cudaFuncAttributeMaxDynamicSharedMemorySize, G2SMEM);

    prep_k<<<13312, 256>>>(x, c0, c1, c2, c3);

    gemm1_k<<<dim3(8, 64, 1), 256, G1SMEM>>>();
    gemm2_k<<<dim3(16, 64, 1), 512, G2SMEM>>>(out, bias);
}

// round 11
// speedup vs baseline: 6.6279x; 1.2064x over previous
#include <cuda_runtime.h>
#include <cuda_fp16.h>
#include <cstdint>

// ===========================================================================
// TR_Linear via fp16 HMMA GEMMs (fp32 accumulate).
//   y[b, 4q+s] = sum_k M1[q,k] * T[b, s*256+k] + bias[4q+s]
//   T = x @ Bmat            (8192x1024)(1024x1024)
// gemm1: CTA 128x128, BK=32, 4-stage single-sync pipeline.      (verified)
// gemm2: CTA 128r x 64q x 4s, 512 thr, B resident, 3-stage A.   (verified)
// prep rebuilt: smem-staged core contractions (kills 32M L1 accesses),
//               x-convert with 16B stores.
// ===========================================================================

__device__ __half g_xh[8192 * 1024];
__device__ __half g_Th[8192 * 1024];
__device__ __half g_Bh[1024 * 1024];   // BmT[n][c]
__device__ __half g_M1[1024 * 256];    // M1[q][k]

// -------------------- helpers ----------------------------------------------
__device__ __forceinline__ uint32_t smem_u32(const void* p) {
    uint32_t a;
    asm("{ .reg .u64 t; cvta.to.shared.u64 t, %1; cvt.u32.u64 %0, t; }" : "=r"(a) : "l"(p));
    return a;
}
__device__ __forceinline__ uint32_t sw64(uint32_t off) { return off ^ ((off >> 3) & 0x30); }

__device__ __forceinline__ void cp16(uint32_t dst, const void* src) {
    asm volatile("cp.async.cg.shared.global [%0], [%1], 16;" :: "r"(dst), "l"(src));
}
__device__ __forceinline__ void cp_commit() { asm volatile("cp.async.commit_group;" ::: "memory"); }
template <int N> __device__ __forceinline__ void cp_wait() {
    asm volatile("cp.async.wait_group %0;" :: "n"(N) : "memory");
}

__device__ __forceinline__ void ldmx4(uint32_t* r, uint32_t addr) {
    asm volatile("ldmatrix.sync.aligned.m8n8.x4.shared.b16 {%0,%1,%2,%3}, [%4];"
                 : "=r"(r[0]), "=r"(r[1]), "=r"(r[2]), "=r"(r[3]) : "r"(addr));
}
__device__ __forceinline__ void mma16816(float* d, const uint32_t* a, uint32_t b0, uint32_t b1) {
    asm volatile(
        "mma.sync.aligned.m16n8k16.row.col.f32.f16.f16.f32 "
        "{%0,%1,%2,%3}, {%4,%5,%6,%7}, {%8,%9}, {%0,%1,%2,%3};"
        : "+f"(d[0]), "+f"(d[1]), "+f"(d[2]), "+f"(d[3])
        : "r"(a[0]), "r"(a[1]), "r"(a[2]), "r"(a[3]), "r"(b0), "r"(b1));
}
__device__ __forceinline__ uint32_t pack2h(float a, float b) {
    __half ha = __float2half_rn(a), hb = __float2half_rn(b);
    return (uint32_t)__half_as_ushort(ha) | ((uint32_t)__half_as_ushort(hb) << 16);
}

// -------------------- prep kernel (smem-staged) -----------------------------
// blocks [0,4096):      x -> fp16, 8 floats/thread (LDG.128 x2, STG.128 x1)
// blocks [4096,5120):   BmT row n: stage core slices in smem, 64 FMA/thread
// blocks [5120,6144):   M1 row q:  stage core slices in smem, 16 FMA/thread
__global__ void prep_k(const float* __restrict__ x,
                       const float* __restrict__ c0, const float* __restrict__ c1,
                       const float* __restrict__ c2, const float* __restrict__ c3) {
    __shared__ float sc[1280];
    int b = blockIdx.x, tid = threadIdx.x;
    if (b < 4096) {
        int i = b * 256 + tid;                     // 1M threads x 8 floats
        const float4* xp = (const float4*)x + (size_t)i * 2;
        float4 v0 = xp[0], v1 = xp[1];
        uint4 o;
        o.x = pack2h(v0.x, v0.y); o.y = pack2h(v0.z, v0.w);
        o.z = pack2h(v1.x, v1.y); o.w = pack2h(v1.z, v1.w);
        ((uint4*)g_xh)[i] = o;
    } else if (b < 5120) {
        // BmT[n][c] = sum_r3 core2[r2, s*16 + c/64, r3] * core3[r3, c%64, r0]
        int n = b - 4096;
        int s = n >> 8, k = n & 255, r2 = k >> 4, r0 = k & 15;
        // sc[o0l*16 + r3] = core2[r2, s*16+o0l, r3]          (256 floats)
        if (tid < 256)
            sc[tid] = __ldg(&c2[(r2 * 64 + s * 16 + (tid >> 4)) * 16 + (tid & 15)]);
        // sc[256 + r3*64 + o1] = core3[r3, o1, r0]           (1024 floats)
        for (int t = tid; t < 1024; t += 256)
            sc[256 + t] = __ldg(&c3[((t >> 6) * 64 + (t & 63)) * 16 + r0]);
        __syncthreads();
#pragma unroll
        for (int t = 0; t < 4; ++t) {
            int c = tid + t * 256;
            int o0l = c >> 6, o1 = c & 63;
            float sum = 0.f;
#pragma unroll
            for (int r3 = 0; r3 < 16; ++r3)
                sum += sc[o0l * 16 + r3] * sc[256 + r3 * 64 + o1];
            g_Bh[(size_t)n * 1024 + c] = __float2half_rn(sum);
        }
    } else {
        // M1[q][k=(r2,r0)] = sum_r1 core0[r0,q0,r1] * core1[r1,q1,r2]
        int q = b - 5120;
        int q0 = q >> 5, q1 = q & 31;
        if (tid < 256) {
            // sc[r0*16+r1] = core0[r0,q0,r1]; sc[256+r1*16+r2] = core1[r1,q1,r2]
            sc[tid]       = __ldg(&c0[((tid >> 4) * 32 + q0) * 16 + (tid & 15)]);
            sc[256 + tid] = __ldg(&c1[((tid >> 4) * 32 + q1) * 16 + (tid & 15)]);
        }
        __syncthreads();
        int r2 = tid >> 4, r0 = tid & 15;
        float sum = 0.f;
#pragma unroll
        for (int r1 = 0; r1 < 16; ++r1)
            sum += sc[r0 * 16 + r1] * sc[256 + r1 * 16 + r2];
        g_M1[(size_t)q * 256 + tid] = __float2half_rn(sum);
    }
}

// ===========================================================================
// GEMM1: T = x @ BmT^T. CTA 128x128, BK=32, 8 warps (2x4), 4-stage
// single-sync pipeline (prefetch distance 2).   [verified round 9]
// ===========================================================================
#define STAGE_BYTES 16384
#define NSTAGES 4
#define G1SMEM (1024 + NSTAGES * STAGE_BYTES)

__global__ void __launch_bounds__(256, 2) gemm1_k() {
    extern __shared__ char smem[];
    const uint32_t db = (smem_u32(smem) + 1023) & ~1023u;
    const int tid = threadIdx.x, lane = tid & 31, wid = tid >> 5;
    const int warp_m = wid & 1, warp_n = wid >> 1;
    const int rowBase = blockIdx.y * 128, colBase = blockIdx.x * 128;

    const __half* A = g_xh + (size_t)rowBase * 1024;
    const __half* B = g_Bh + (size_t)colBase * 1024;

    auto load_chunk = [&](int kc, int buf) {
        uint32_t base = db + buf * STAGE_BYTES;
#pragma unroll
        for (int it = 0; it < 2; ++it) {
            int idx = tid + it * 256;
            int row = idx >> 2, c16 = idx & 3;
            uint32_t so = sw64((uint32_t)(row * 64 + c16 * 16));
            cp16(base + so,        A + row * 1024 + kc * 32 + c16 * 8);
            cp16(base + 8192 + so, B + row * 1024 + kc * 32 + c16 * 8);
        }
        cp_commit();
    };

    float acc[4][4][4];
#pragma unroll
    for (int i = 0; i < 4; ++i)
#pragma unroll
        for (int j = 0; j < 4; ++j)
#pragma unroll
            for (int t = 0; t < 4; ++t) acc[i][j][t] = 0.f;

    const int rowA = warp_m * 64 + (lane & 15);
    const int a_c16half = (lane >> 4) & 1;
    const int rowB = warp_n * 32 + (lane & 7) + ((lane >> 4) << 3);
    const int b_c16half = (lane >> 3) & 1;

    load_chunk(0, 0);
    load_chunk(1, 1);

    for (int i = 0; i < 32; ++i) {
        if (i + 2 < 32) load_chunk(i + 2, (i + 2) & (NSTAGES - 1));
        if (i < 30)       cp_wait<2>();
        else if (i == 30) cp_wait<1>();
        else              cp_wait<0>();
        __syncthreads();

        uint32_t base = db + (i & (NSTAGES - 1)) * STAGE_BYTES;
#pragma unroll
        for (int ks = 0; ks < 2; ++ks) {
            uint32_t a[4][4];
#pragma unroll
            for (int mt = 0; mt < 4; ++mt) {
                uint32_t off = sw64((uint32_t)((rowA + mt * 16) * 64 + (ks * 2 + a_c16half) * 16));
                ldmx4(a[mt], base + off);
            }
            uint32_t b[4][2];
#pragma unroll
            for (int nt = 0; nt < 2; ++nt) {
                uint32_t off = sw64((uint32_t)((rowB + nt * 16) * 64 + (ks * 2 + b_c16half) * 16));
                uint32_t r[4];
                ldmx4(r, base + 8192 + off);
                b[nt * 2][0] = r[0];     b[nt * 2][1] = r[1];
                b[nt * 2 + 1][0] = r[2]; b[nt * 2 + 1][1] = r[3];
            }
#pragma unroll
            for (int mt = 0; mt < 4; ++mt)
#pragma unroll
                for (int j = 0; j < 4; ++j)
                    mma16816(acc[mt][j], a[mt], b[j][0], b[j][1]);
        }
    }

    const int r0base = rowBase + warp_m * 64 + (lane >> 2);
    const int cbase  = colBase + warp_n * 32 + (lane & 3) * 2;
#pragma unroll
    for (int mt = 0; mt < 4; ++mt)
#pragma unroll
        for (int j = 0; j < 4; ++j) {
            int r0 = r0base + mt * 16;
            int c  = cbase + j * 8;
            *(uint32_t*)(g_Th + (size_t)r0 * 1024 + c) =
                pack2h(acc[mt][j][0], acc[mt][j][1]);
            *(uint32_t*)(g_Th + (size_t)(r0 + 8) * 1024 + c) =
                pack2h(acc[mt][j][2], acc[mt][j][3]);
        }
}

// ===========================================================================
// GEMM2: out[b, 4q+s] = sum_k T[b, s*256+k] * M1[q,k] + bias
// CTA: 128 rows x 64 q x 4 s (256 contiguous out cols), 512 threads.
// [verified round 9]
// ===========================================================================
#define EPI_PITCH 268
#define G2SMEM (1024 + 32768 + 3 * 32768)

__global__ void __launch_bounds__(512, 1) gemm2_k(float* __restrict__ Out,
                                                  const float* __restrict__ bias) {
    extern __shared__ char smem[];
    const uint32_t db = (smem_u32(smem) + 1023) & ~1023u;
    const uint32_t Bs = db;
    const uint32_t As = db + 32768;
    const int tid = threadIdx.x, lane = tid & 31, wid = tid >> 5;
    const int warp_m = wid & 1, warp_q = (wid >> 1) & 1, warp_s = wid >> 2;
    const int rowBase = blockIdx.y * 128, qBase = blockIdx.x * 64;

    const __half* A  = g_Th + (size_t)rowBase * 1024;
    const __half* Bm = g_M1 + (size_t)qBase * 256;

#pragma unroll
    for (int it = 0; it < 4; ++it) {
        int idx = tid + it * 512;
        int kc = idx >> 8;
        int r  = (idx >> 2) & 63;
        int c  = idx & 3;
        cp16(Bs + kc * 4096 + sw64((uint32_t)(r * 64 + c * 16)),
             Bm + r * 256 + kc * 32 + c * 8);
    }

    auto loadA = [&](int kc, int buf) {
        uint32_t base = As + buf * 32768;
#pragma unroll
        for (int it = 0; it < 4; ++it) {
            int idx = tid + it * 512;
            int s   = idx >> 9;
            int row = (idx >> 2) & 127, c16 = idx & 3;
            cp16(base + s * 8192 + sw64((uint32_t)(row * 64 + c16 * 16)),
                 A + row * 1024 + s * 256 + kc * 32 + c16 * 8);
        }
        cp_commit();
    };

    loadA(0, 0);

    float acc[4][4][4];
#pragma unroll
    for (int i = 0; i < 4; ++i)
#pragma unroll
        for (int j = 0; j < 4; ++j)
#pragma unroll
            for (int t = 0; t < 4; ++t) acc[i][j][t] = 0.f;

    const int rowA = warp_m * 64 + (lane & 15);
    const int a_c16half = (lane >> 4) & 1;
    const int rowB = warp_q * 32 + (lane & 7) + ((lane >> 4) << 3);
    const int b_c16half = (lane >> 3) & 1;

    int bufi = 0;
    for (int i = 0; i < 8; ++i) {
        if (i + 1 < 8) {
            int nb = bufi + 1; if (nb == 3) nb = 0;
            loadA(i + 1, nb);
        }
        if (i < 7) cp_wait<1>(); else cp_wait<0>();
        __syncthreads();

        uint32_t abase = As + bufi * 32768 + warp_s * 8192;
        uint32_t bbase = Bs + i * 4096;
#pragma unroll
        for (int ks = 0; ks < 2; ++ks) {
            uint32_t a[4][4];
#pragma unroll
            for (int mt = 0; mt < 4; ++mt) {
                uint32_t off = sw64((uint32_t)((rowA + mt * 16) * 64 + (ks * 2 + a_c16half) * 16));
                ldmx4(a[mt], abase + off);
            }
            uint32_t b[4][2];
#pragma unroll
            for (int nt = 0; nt < 2; ++nt) {
                uint32_t off = sw64((uint32_t)((rowB + nt * 16) * 64 + (ks * 2 + b_c16half) * 16));
                uint32_t r[4];
                ldmx4(r, bbase + off);
                b[nt * 2][0] = r[0];     b[nt * 2][1] = r[1];
                b[nt * 2 + 1][0] = r[2]; b[nt * 2 + 1][1] = r[3];
            }
#pragma unroll
            for (int mt = 0; mt < 4; ++mt)
#pragma unroll
                for (int j = 0; j < 4; ++j)
                    mma16816(acc[mt][j], a[mt], b[j][0], b[j][1]);
        }
        if (++bufi == 3) bufi = 0;
    }

    const int cbase = qBase * 4;
#pragma unroll
    for (int p = 0; p < 2; ++p) {
        __syncthreads();
        if (warp_m == p) {
            const int brow0 = (lane >> 2);
            const int qloc0 = warp_q * 32 + (lane & 3) * 2;
#pragma unroll
            for (int mt = 0; mt < 4; ++mt)
#pragma unroll
                for (int j = 0; j < 4; ++j) {
                    int br = brow0 + mt * 16;
                    int q0 = qloc0 + j * 8;
                    uint32_t a0 = As + (uint32_t)(br       * EPI_PITCH + 4 * q0 + warp_s) * 4;
                    uint32_t a1 = As + (uint32_t)(br       * EPI_PITCH + 4 * (q0 + 1) + warp_s) * 4;
                    uint32_t a2 = As + (uint32_t)((br + 8) * EPI_PITCH + 4 * q0 + warp_s) * 4;
                    uint32_t a3 = As + (uint32_t)((br + 8) * EPI_PITCH + 4 * (q0 + 1) + warp_s) * 4;
                    asm volatile("st.shared.f32 [%0], %1;" :: "r"(a0), "f"(acc[mt][j][0]));
                    asm volatile("st.shared.f32 [%0], %1;" :: "r"(a1), "f"(acc[mt][j][1]));
                    asm volatile("st.shared.f32 [%0], %1;" :: "r"(a2), "f"(acc[mt][j][2]));
                    asm volatile("st.shared.f32 [%0], %1;" :: "r"(a3), "f"(acc[mt][j][3]));
                }
        }
        __syncthreads();
#pragma unroll
        for (int it = 0; it < 8; ++it) {
            int idx = tid + it * 512;
            int row = idx >> 6, col4 = idx & 63;
            float4 v;
            uint32_t sa = As + (uint32_t)(row * EPI_PITCH + col4 * 4) * 4;
            asm volatile("ld.shared.v4.f32 {%0,%1,%2,%3}, [%4];"
                         : "=f"(v.x), "=f"(v.y), "=f"(v.z), "=f"(v.w) : "r"(sa));
            float4 bb = __ldg((const float4*)(bias + cbase + col4 * 4));
            v.x += bb.x; v.y += bb.y; v.z += bb.z; v.w += bb.w;
            *(float4*)(Out + (size_t)(rowBase + p * 64 + row) * 4096 + cbase + col4 * 4) = v;
        }
    }
}

// ---------------------------------------------------------------------------
extern "C" void kernel_launch(void* const* d_in, const int* in_sizes, int n_in,
                              void* d_out, int out_size)
{
    const float* x    = (const float*)d_in[0];
    const float* c0   = (const float*)d_in[1];
    const float* c1   = (const float*)d_in[2];
    const float* c2   = (const float*)d_in[3];
    const float* c3   = (const float*)d_in[4];
    const float* bias = (const float*)d_in[5];
    float* out = (float*)d_out;

    cudaFuncSetAttribute(gemm1_k, cudaFuncAttributeMaxDynamicSharedMemorySize, G1SMEM);
    cudaFuncSetAttribute(gemm2_k, cudaFuncAttributeMaxDynamicSharedMemorySize, G2SMEM);

    prep_k<<<6144, 256>>>(x, c0, c1, c2, c3);

    gemm1_k<<<dim3(8, 64, 1), 256, G1SMEM>>>();
    gemm2_k<<<dim3(16, 64, 1), 512, G2SMEM>>>(out, bias);
}

// round 13
// speedup vs baseline: 7.1175x; 1.0739x over previous
#include <cuda_runtime.h>
#include <cuda_fp16.h>
#include <cstdint>

// ===========================================================================
// TR_Linear via fp16 HMMA GEMMs (fp32 accumulate).
//   y[b, 4q+s] = sum_k M1[q,k] * T[b, s*256+k] + bias[4q+s]
//   T = x @ Bmat            (8192x1024)(1024x1024)
// gemm1: CTA 128x128, BK=32, 4-stage single-sync pipeline.      (verified)
// gemm2 v2: CTA 64r x 64q x 4s, 256 thr, ~110 regs -> 2 CTAs/SM so
//           epilogue/pipeline-fill of one CTA overlaps MMAs of the other.
// prep: smem-staged core contractions.                           (verified)
// ===========================================================================

__device__ __half g_xh[8192 * 1024];
__device__ __half g_Th[8192 * 1024];
__device__ __half g_Bh[1024 * 1024];   // BmT[n][c]
__device__ __half g_M1[1024 * 256];    // M1[q][k]

// -------------------- helpers ----------------------------------------------
__device__ __forceinline__ uint32_t smem_u32(const void* p) {
    uint32_t a;
    asm("{ .reg .u64 t; cvta.to.shared.u64 t, %1; cvt.u32.u64 %0, t; }" : "=r"(a) : "l"(p));
    return a;
}
__device__ __forceinline__ uint32_t sw64(uint32_t off) { return off ^ ((off >> 3) & 0x30); }

__device__ __forceinline__ void cp16(uint32_t dst, const void* src) {
    asm volatile("cp.async.cg.shared.global [%0], [%1], 16;" :: "r"(dst), "l"(src));
}
__device__ __forceinline__ void cp_commit() { asm volatile("cp.async.commit_group;" ::: "memory"); }
template <int N> __device__ __forceinline__ void cp_wait() {
    asm volatile("cp.async.wait_group %0;" :: "n"(N) : "memory");
}

__device__ __forceinline__ void ldmx4(uint32_t* r, uint32_t addr) {
    asm volatile("ldmatrix.sync.aligned.m8n8.x4.shared.b16 {%0,%1,%2,%3}, [%4];"
                 : "=r"(r[0]), "=r"(r[1]), "=r"(r[2]), "=r"(r[3]) : "r"(addr));
}
__device__ __forceinline__ void mma16816(float* d, const uint32_t* a, uint32_t b0, uint32_t b1) {
    asm volatile(
        "mma.sync.aligned.m16n8k16.row.col.f32.f16.f16.f32 "
        "{%0,%1,%2,%3}, {%4,%5,%6,%7}, {%8,%9}, {%0,%1,%2,%3};"
        : "+f"(d[0]), "+f"(d[1]), "+f"(d[2]), "+f"(d[3])
        : "r"(a[0]), "r"(a[1]), "r"(a[2]), "r"(a[3]), "r"(b0), "r"(b1));
}
__device__ __forceinline__ uint32_t pack2h(float a, float b) {
    __half ha = __float2half_rn(a), hb = __float2half_rn(b);
    return (uint32_t)__half_as_ushort(ha) | ((uint32_t)__half_as_ushort(hb) << 16);
}

// -------------------- prep kernel (smem-staged, verified R11) ---------------
__global__ void prep_k(const float* __restrict__ x,
                       const float* __restrict__ c0, const float* __restrict__ c1,
                       const float* __restrict__ c2, const float* __restrict__ c3) {
    __shared__ float sc[1280];
    int b = blockIdx.x, tid = threadIdx.x;
    if (b < 4096) {
        int i = b * 256 + tid;
        const float4* xp = (const float4*)x + (size_t)i * 2;
        float4 v0 = xp[0], v1 = xp[1];
        uint4 o;
        o.x = pack2h(v0.x, v0.y); o.y = pack2h(v0.z, v0.w);
        o.z = pack2h(v1.x, v1.y); o.w = pack2h(v1.z, v1.w);
        ((uint4*)g_xh)[i] = o;
    } else if (b < 5120) {
        int n = b - 4096;
        int s = n >> 8, k = n & 255, r2 = k >> 4, r0 = k & 15;
        if (tid < 256)
            sc[tid] = __ldg(&c2[(r2 * 64 + s * 16 + (tid >> 4)) * 16 + (tid & 15)]);
        for (int t = tid; t < 1024; t += 256)
            sc[256 + t] = __ldg(&c3[((t >> 6) * 64 + (t & 63)) * 16 + r0]);
        __syncthreads();
#pragma unroll
        for (int t = 0; t < 4; ++t) {
            int c = tid + t * 256;
            int o0l = c >> 6, o1 = c & 63;
            float sum = 0.f;
#pragma unroll
            for (int r3 = 0; r3 < 16; ++r3)
                sum += sc[o0l * 16 + r3] * sc[256 + r3 * 64 + o1];
            g_Bh[(size_t)n * 1024 + c] = __float2half_rn(sum);
        }
    } else {
        int q = b - 5120;
        int q0 = q >> 5, q1 = q & 31;
        if (tid < 256) {
            sc[tid]       = __ldg(&c0[((tid >> 4) * 32 + q0) * 16 + (tid & 15)]);
            sc[256 + tid] = __ldg(&c1[((tid >> 4) * 32 + q1) * 16 + (tid & 15)]);
        }
        __syncthreads();
        int r2 = tid >> 4, r0 = tid & 15;
        float sum = 0.f;
#pragma unroll
        for (int r1 = 0; r1 < 16; ++r1)
            sum += sc[r0 * 16 + r1] * sc[256 + r1 * 16 + r2];
        g_M1[(size_t)q * 256 + tid] = __float2half_rn(sum);
    }
}

// ===========================================================================
// GEMM1: T = x @ BmT^T. CTA 128x128, BK=32, 8 warps (2x4), 4-stage
// single-sync pipeline. [verified]
// ===========================================================================
#define STAGE_BYTES 16384
#define NSTAGES 4
#define G1SMEM (1024 + NSTAGES * STAGE_BYTES)

__global__ void __launch_bounds__(256, 2) gemm1_k() {
    extern __shared__ char smem[];
    const uint32_t db = (smem_u32(smem) + 1023) & ~1023u;
    const int tid = threadIdx.x, lane = tid & 31, wid = tid >> 5;
    const int warp_m = wid & 1, warp_n = wid >> 1;
    const int rowBase = blockIdx.y * 128, colBase = blockIdx.x * 128;

    const __half* A = g_xh + (size_t)rowBase * 1024;
    const __half* B = g_Bh + (size_t)colBase * 1024;

    auto load_chunk = [&](int kc, int buf) {
        uint32_t base = db + buf * STAGE_BYTES;
#pragma unroll
        for (int it = 0; it < 2; ++it) {
            int idx = tid + it * 256;
            int row = idx >> 2, c16 = idx & 3;
            uint32_t so = sw64((uint32_t)(row * 64 + c16 * 16));
            cp16(base + so,        A + row * 1024 + kc * 32 + c16 * 8);
            cp16(base + 8192 + so, B + row * 1024 + kc * 32 + c16 * 8);
        }
        cp_commit();
    };

    float acc[4][4][4];
#pragma unroll
    for (int i = 0; i < 4; ++i)
#pragma unroll
        for (int j = 0; j < 4; ++j)
#pragma unroll
            for (int t = 0; t < 4; ++t) acc[i][j][t] = 0.f;

    const int rowA = warp_m * 64 + (lane & 15);
    const int a_c16half = (lane >> 4) & 1;
    const int rowB = warp_n * 32 + (lane & 7) + ((lane >> 4) << 3);
    const int b_c16half = (lane >> 3) & 1;

    load_chunk(0, 0);
    load_chunk(1, 1);

    for (int i = 0; i < 32; ++i) {
        if (i + 2 < 32) load_chunk(i + 2, (i + 2) & (NSTAGES - 1));
        if (i < 30)       cp_wait<2>();
        else if (i == 30) cp_wait<1>();
        else              cp_wait<0>();
        __syncthreads();

        uint32_t base = db + (i & (NSTAGES - 1)) * STAGE_BYTES;
#pragma unroll
        for (int ks = 0; ks < 2; ++ks) {
            uint32_t a[4][4];
#pragma unroll
            for (int mt = 0; mt < 4; ++mt) {
                uint32_t off = sw64((uint32_t)((rowA + mt * 16) * 64 + (ks * 2 + a_c16half) * 16));
                ldmx4(a[mt], base + off);
            }
            uint32_t b[4][2];
#pragma unroll
            for (int nt = 0; nt < 2; ++nt) {
                uint32_t off = sw64((uint32_t)((rowB + nt * 16) * 64 + (ks * 2 + b_c16half) * 16));
                uint32_t r[4];
                ldmx4(r, base + 8192 + off);
                b[nt * 2][0] = r[0];     b[nt * 2][1] = r[1];
                b[nt * 2 + 1][0] = r[2]; b[nt * 2 + 1][1] = r[3];
            }
#pragma unroll
            for (int mt = 0; mt < 4; ++mt)
#pragma unroll
                for (int j = 0; j < 4; ++j)
                    mma16816(acc[mt][j], a[mt], b[j][0], b[j][1]);
        }
    }

    const int r0base = rowBase + warp_m * 64 + (lane >> 2);
    const int cbase  = colBase + warp_n * 32 + (lane & 3) * 2;
#pragma unroll
    for (int mt = 0; mt < 4; ++mt)
#pragma unroll
        for (int j = 0; j < 4; ++j) {
            int r0 = r0base + mt * 16;
            int c  = cbase + j * 8;
            *(uint32_t*)(g_Th + (size_t)r0 * 1024 + c) =
                pack2h(acc[mt][j][0], acc[mt][j][1]);
            *(uint32_t*)(g_Th + (size_t)(r0 + 8) * 1024 + c) =
                pack2h(acc[mt][j][2], acc[mt][j][3]);
        }
}

// ===========================================================================
// GEMM2 v2: out[b, 4q+s] = sum_k T[b, s*256+k] * M1[q,k] + bias
// CTA: 64 rows x 64 q x 4 s (256 contiguous out cols), 256 threads.
// 8 warps: warp_q = wid&1, warp_s = wid>>1. Warp tile 64r x 32q, K=256.
// smem: B resident 32KB (8 kc-subtiles of 64q x 64B SW64);
//       A 3-stage x 16KB (4 s x 64r x 64B SW64), single-sync, dist-1;
//       epilogue reuses A region: 4 phases of 16 rows x pitch-260 fp32.
// ~110 regs, 82KB smem -> 2 CTAs/SM: epilogue overlaps peer CTA's MMAs.
// ===========================================================================
#define A2_STAGE 16384
#define EPI_PITCH 260
#define G2SMEM (1024 + 32768 + 3 * A2_STAGE)

__global__ void __launch_bounds__(256, 2) gemm2_k(float* __restrict__ Out,
                                                  const float* __restrict__ bias) {
    extern __shared__ char smem[];
    const uint32_t db = (smem_u32(smem) + 1023) & ~1023u;
    const uint32_t Bs = db;             // 32KB resident B
    const uint32_t As = db + 32768;     // 3 x 16KB A stages / epilogue buffer
    const int tid = threadIdx.x, lane = tid & 31, wid = tid >> 5;
    const int warp_q = wid & 1, warp_s = wid >> 1;
    const int rowBase = blockIdx.y * 64, qBase = blockIdx.x * 64;

    const __half* A  = g_Th + (size_t)rowBase * 1024;  // 64 rows x [s*256+k]
    const __half* Bm = g_M1 + (size_t)qBase * 256;     // 64 q x 256 k

    // --- resident B: 8 kc-subtiles of 64 rows x 64B (32KB, 2048 cp16) ---
#pragma unroll
    for (int it = 0; it < 8; ++it) {
        int idx = tid + it * 256;          // 0..2047
        int kc = idx >> 8;                 // 0..7
        int r  = (idx >> 2) & 63;
        int c  = idx & 3;
        cp16(Bs + kc * 4096 + sw64((uint32_t)(r * 64 + c * 16)),
             Bm + r * 256 + kc * 32 + c * 8);
    }

    // --- A stage: 4 s-subtiles x 64 rows x 32 k (16KB, 1024 cp16) ---
    auto loadA = [&](int kc, int buf) {
        uint32_t base = As + buf * A2_STAGE;
#pragma unroll
        for (int it = 0; it < 4; ++it) {
            int idx = tid + it * 256;      // 0..1023
            int s   = idx >> 8;
            int row = (idx >> 2) & 63, c16 = idx & 3;
            cp16(base + s * 4096 + sw64((uint32_t)(row * 64 + c16 * 16)),
                 A + row * 1024 + s * 256 + kc * 32 + c16 * 8);
        }
        cp_commit();
    };

    loadA(0, 0);   // group 0 = B + A chunk 0

    float acc[4][4][4];
#pragma unroll
    for (int i = 0; i < 4; ++i)
#pragma unroll
        for (int j = 0; j < 4; ++j)
#pragma unroll
            for (int t = 0; t < 4; ++t) acc[i][j][t] = 0.f;

    const int rowA = lane & 15;                                   // + mt*16
    const int a_c16half = (lane >> 4) & 1;
    const int rowB = warp_q * 32 + (lane & 7) + ((lane >> 4) << 3);
    const int b_c16half = (lane >> 3) & 1;

    int bufi = 0;
    for (int i = 0; i < 8; ++i) {
        if (i + 1 < 8) {
            int nb = bufi + 1; if (nb == 3) nb = 0;
            loadA(i + 1, nb);
        }
        if (i < 7) cp_wait<1>(); else cp_wait<0>();
        __syncthreads();

        uint32_t abase = As + bufi * A2_STAGE + warp_s * 4096;
        uint32_t bbase = Bs + i * 4096;
#pragma unroll
        for (int ks = 0; ks < 2; ++ks) {
            uint32_t a[4][4];
#pragma unroll
            for (int mt = 0; mt < 4; ++mt) {
                uint32_t off = sw64((uint32_t)((rowA + mt * 16) * 64 + (ks * 2 + a_c16half) * 16));
                ldmx4(a[mt], abase + off);
            }
            uint32_t b[4][2];
#pragma unroll
            for (int nt = 0; nt < 2; ++nt) {
                uint32_t off = sw64((uint32_t)((rowB + nt * 16) * 64 + (ks * 2 + b_c16half) * 16));
                uint32_t r[4];
                ldmx4(r, bbase + off);
                b[nt * 2][0] = r[0];     b[nt * 2][1] = r[1];
                b[nt * 2 + 1][0] = r[2]; b[nt * 2 + 1][1] = r[3];
            }
#pragma unroll
            for (int mt = 0; mt < 4; ++mt)
#pragma unroll
                for (int j = 0; j < 4; ++j)
                    mma16816(acc[mt][j], a[mt], b[j][0], b[j][1]);
        }
        if (++bufi == 3) bufi = 0;
    }

    // --- epilogue: 4 phases of 16 rows (mt = p), pitch-260 interleave ------
    const int cbase = qBase * 4;           // 256 contiguous out cols
#pragma unroll
    for (int p = 0; p < 4; ++p) {
        __syncthreads();                   // mainloop reads (or prev phase) done
        {
            const int brow0 = (lane >> 2);             // rows brow0, brow0+8
            const int qloc0 = warp_q * 32 + (lane & 3) * 2;
#pragma unroll
            for (int j = 0; j < 4; ++j) {
                int q0 = qloc0 + j * 8;
                uint32_t a0 = As + (uint32_t)(brow0       * EPI_PITCH + 4 * q0 + warp_s) * 4;
                uint32_t a1 = As + (uint32_t)(brow0       * EPI_PITCH + 4 * (q0 + 1) + warp_s) * 4;
                uint32_t a2 = As + (uint32_t)((brow0 + 8) * EPI_PITCH + 4 * q0 + warp_s) * 4;
                uint32_t a3 = As + (uint32_t)((brow0 + 8) * EPI_PITCH + 4 * (q0 + 1) + warp_s) * 4;
                asm volatile("st.shared.f32 [%0], %1;" :: "r"(a0), "f"(acc[p][j][0]));
                asm volatile("st.shared.f32 [%0], %1;" :: "r"(a1), "f"(acc[p][j][1]));
                asm volatile("st.shared.f32 [%0], %1;" :: "r"(a2), "f"(acc[p][j][2]));
                asm volatile("st.shared.f32 [%0], %1;" :: "r"(a3), "f"(acc[p][j][3]));
            }
        }
        __syncthreads();
        // coalesced float4 stores with bias: 16 rows x 64 float4s
#pragma unroll
        for (int it = 0; it < 4; ++it) {
            int idx = tid + it * 256;      // 0..1023
            int row = idx >> 6, col4 = idx & 63;
            float4 v;
            uint32_t sa = As + (uint32_t)(row * EPI_PITCH + col4 * 4) * 4;
            asm volatile("ld.shared.v4.f32 {%0,%1,%2,%3}, [%4];"
                         : "=f"(v.x), "=f"(v.y), "=f"(v.z), "=f"(v.w) : "r"(sa));
            float4 bb = __ldg((const float4*)(bias + cbase + col4 * 4));
            v.x += bb.x; v.y += bb.y; v.z += bb.z; v.w += bb.w;
            *(float4*)(Out + (size_t)(rowBase + p * 16 + row) * 4096 + cbase + col4 * 4) = v;
        }
    }
}

// ---------------------------------------------------------------------------
extern "C" void kernel_launch(void* const* d_in, const int* in_sizes, int n_in,
                              void* d_out, int out_size)
{
    const float* x    = (const float*)d_in[0];
    const float* c0   = (const float*)d_in[1];
    const float* c1   = (const float*)d_in[2];
    const float* c2   = (const float*)d_in[3];
    const float* c3   = (const float*)d_in[4];
    const float* bias = (const float*)d_in[5];
    float* out = (float*)d_out;

    cudaFuncSetAttribute(gemm1_k, cudaFuncAttributeMaxDynamicSharedMemorySize, G1SMEM);
    cudaFuncSetAttribute(gemm2_k, cudaFuncAttributeMaxDynamicSharedMemorySize, G2SMEM);

    prep_k<<<6144, 256>>>(x, c0, c1, c2, c3);

    gemm1_k<<<dim3(8, 64, 1), 256, G1SMEM>>>();
    gemm2_k<<<dim3(16, 128, 1), 256, G2SMEM>>>(out, bias);
}